// round 13
// baseline (speedup 1.0000x reference)
#include <cuda_runtime.h>
#include <math.h>
#include <stdint.h>

// Problem dims
#define BATCH 8192
#define OBS 64
#define ACT 16
#define HID 128
#define CON 256
#define COMP 85
#define KS 32

// ---------------- scratch (device globals; no allocation) ----------------
__device__ float g_G[COMP * COMP];          // W1 W1^T
__device__ float g_W3T[COMP * COMP];        // mw3 transposed
__device__ float g_fout[BATCH * COMP];      // f-net output (relu(p3))
__device__ float g_kout[BATCH];             // k-net output (softplus)
__device__ unsigned g_d1m[BATCH * 3];       // d1 bitmask (85 bits in 3 words)
__device__ unsigned g_d2m[BATCH * 3];       // d2 bitmask

// ---- cp.async helpers ----
__device__ __forceinline__ void cpa4(uint32_t dst_smem, const float* src) {
    asm volatile("cp.async.ca.shared.global [%0], [%1], 4;"
                 :: "r"(dst_smem), "l"(src));
}
__device__ __forceinline__ void cpa_commit() {
    asm volatile("cp.async.commit_group;" ::: "memory");
}
template<int N>
__device__ __forceinline__ void cpa_wait() {
    asm volatile("cp.async.wait_group %0;" :: "n"(N) : "memory");
}

// =========================================================================
// Kernel 1: G = mw1 @ mw1^T (warp per element) + W3 transpose
// =========================================================================
__global__ __launch_bounds__(256)
void g_kernel(const float* __restrict__ mw1, const float* __restrict__ mw3) {
    int gid = blockIdx.x * 256 + threadIdx.x;
    if (gid < COMP * COMP) {
        int r = gid / COMP, c = gid - r * COMP;
        g_W3T[c * COMP + r] = mw3[gid];
    }
    int gw = gid >> 5;   // global warp id
    int lane = threadIdx.x & 31;
    if (gw >= COMP * COMP) return;
    int i = gw / COMP;
    int j = gw - i * COMP;
    const float4* a = (const float4*)(mw1 + i * CON);
    const float4* b = (const float4*)(mw1 + j * CON);
    float acc = 0.f;
    #pragma unroll
    for (int t = 0; t < 2; t++) {
        float4 av = a[lane + 32 * t];
        float4 bv = b[lane + 32 * t];
        acc += av.x * bv.x + av.y * bv.y + av.z * bv.z + av.w * bv.w;
    }
    #pragma unroll
    for (int off = 16; off; off >>= 1)
        acc += __shfl_down_sync(0xFFFFFFFFu, acc, off);
    if (lane == 0) g_G[gw] = acc;
}

// =========================================================================
// Kernel 2: fused forward pass. 64 samples per CTA, 512 threads.
// =========================================================================
#define TS 64
#define FWD_THREADS 512

// smem layout (float offsets)
#define O_X   0            // x buffer 64 x 257 (concat of/af)
#define XS    257
#define O_W   16448        // weight staging 16512 floats
#define O_T   32960        // head layer-1 temp 64 x 129
#define TBS   129
#define O_IN  41216        // input staging 64 x 65 (also k1/k2 bufs)
#define O_K1  41216        // k1: 64 x 33
#define O_K2  43328        // k2: 64 x 17
#define O_H1  45376        // h1 / f_out: 64 x 87
#define O_H2  50944        // h2: 64 x 87
#define HS    87
#define FWD_SMEM_FLOATS 56512
#define FWD_SMEM_BYTES  (FWD_SMEM_FLOATS * 4)

#define ACT_RELU 0
#define ACT_TANH 1

template<int N, int K, int ACTT>
__device__ __forceinline__ void layer_fwd(
    float* __restrict__ sm,
    int o_out, int outStride, int outColOff,
    int o_in, int inStride,
    const float* __restrict__ Wg, const float* __restrict__ bg)
{
    constexpr int NJ = (N + 31) / 32;
    const int tid = threadIdx.x;
    const int sp = tid >> 5;       // 0..15, samples 4sp..4sp+3
    const int q = tid & 31;        // output col group

    float acc[4][NJ];
    #pragma unroll
    for (int s = 0; s < 4; s++)
        #pragma unroll
        for (int j = 0; j < NJ; j++) acc[s][j] = 0.f;

    float* wbuf = sm + O_W;
    constexpr int KC = (K > 128) ? 128 : K;
    constexpr int WS = KC | 1;     // odd stride -> conflict-free weight columns

    #pragma unroll
    for (int k0 = 0; k0 < K; k0 += KC) {
        __syncthreads();
        {
            constexpr int TOT = N * KC;
            constexpr int NIT = (TOT + FWD_THREADS - 1) / FWD_THREADS;
            int i = tid;
            #pragma unroll
            for (int u = 0; u < NIT; u++) {
                if (i < TOT) {
                    int r = i / KC;
                    int c = i - r * KC;
                    wbuf[r * WS + c] = Wg[r * K + k0 + c];
                }
                i += FWD_THREADS;
            }
        }
        __syncthreads();
        const float* in0 = sm + o_in + (4 * sp + 0) * inStride + k0;
        const float* in1 = sm + o_in + (4 * sp + 1) * inStride + k0;
        const float* in2 = sm + o_in + (4 * sp + 2) * inStride + k0;
        const float* in3 = sm + o_in + (4 * sp + 3) * inStride + k0;
        #pragma unroll 2
        for (int k = 0; k < KC; k++) {
            float a0 = in0[k], a1 = in1[k], a2 = in2[k], a3 = in3[k];
            const float* wr = wbuf + k + q * WS;
            #pragma unroll
            for (int j = 0; j < NJ; j++) {
                float w = wr[(j << 5) * WS];
                acc[0][j] = fmaf(a0, w, acc[0][j]);
                acc[1][j] = fmaf(a1, w, acc[1][j]);
                acc[2][j] = fmaf(a2, w, acc[2][j]);
                acc[3][j] = fmaf(a3, w, acc[3][j]);
            }
        }
    }
    #pragma unroll
    for (int j = 0; j < NJ; j++) {
        int o = q + (j << 5);
        if (o < N) {
            float bv = bg[o];
            #pragma unroll
            for (int s = 0; s < 4; s++) {
                float v = acc[s][j] + bv;
                if (ACTT == ACT_RELU) v = fmaxf(v, 0.f);
                else if (ACTT == ACT_TANH) v = tanhf(v);
                sm[o_out + (4 * sp + s) * outStride + outColOff + o] = v;
            }
        }
    }
    __syncthreads();
}

__global__ __launch_bounds__(FWD_THREADS)
void fwd_kernel(
    const float* __restrict__ obs, const float* __restrict__ action,
    const float* __restrict__ ow1, const float* __restrict__ ob1,
    const float* __restrict__ ow2, const float* __restrict__ ob2,
    const float* __restrict__ aw1, const float* __restrict__ ab1,
    const float* __restrict__ aw2, const float* __restrict__ ab2,
    const float* __restrict__ mw1, const float* __restrict__ mb1,
    const float* __restrict__ mw2, const float* __restrict__ mb2,
    const float* __restrict__ mw3, const float* __restrict__ mb3,
    const float* __restrict__ kw1, const float* __restrict__ kb1,
    const float* __restrict__ kw2, const float* __restrict__ kb2,
    const float* __restrict__ kw3, const float* __restrict__ kb3)
{
    extern __shared__ float sm[];
    const int tid = threadIdx.x;
    const int sbase = blockIdx.x * TS;

    for (int i = tid; i < TS * OBS; i += FWD_THREADS) {
        int s = i >> 6, k = i & 63;
        sm[O_IN + s * 65 + k] = obs[(sbase + s) * OBS + k];
    }
    __syncthreads();
    layer_fwd<HID, OBS, ACT_RELU>(sm, O_T, TBS, 0, O_IN, 65, ow1, ob1);
    layer_fwd<HID, HID, ACT_RELU>(sm, O_X, XS, 0, O_T, TBS, ow2, ob2);

    for (int i = tid; i < TS * ACT; i += FWD_THREADS) {
        int s = i >> 4, k = i & 15;
        sm[O_IN + s * 17 + k] = action[(sbase + s) * ACT + k];
    }
    __syncthreads();
    layer_fwd<HID, ACT, ACT_RELU>(sm, O_T, TBS, 0, O_IN, 17, aw1, ab1);
    layer_fwd<HID, HID, ACT_RELU>(sm, O_X, XS, 128, O_T, TBS, aw2, ab2);

    layer_fwd<COMP, CON, ACT_RELU>(sm, O_H1, HS, 0, O_X, XS, mw1, mb1);
    if (tid < TS * 3) {
        int s = tid / 3, w = tid - 3 * s;
        unsigned m = 0;
        for (int b = 0; b < 32; b++) {
            int idx = w * 32 + b;
            if (idx < COMP && sm[O_H1 + s * HS + idx] > 0.f) m |= 1u << b;
        }
        g_d1m[(sbase + s) * 3 + w] = m;
    }
    layer_fwd<COMP, COMP, ACT_RELU>(sm, O_H2, HS, 0, O_H1, HS, mw2, mb2);
    if (tid < TS * 3) {
        int s = tid / 3, w = tid - 3 * s;
        unsigned m = 0;
        for (int b = 0; b < 32; b++) {
            int idx = w * 32 + b;
            if (idx < COMP && sm[O_H2 + s * HS + idx] > 0.f) m |= 1u << b;
        }
        g_d2m[(sbase + s) * 3 + w] = m;
    }
    layer_fwd<COMP, COMP, ACT_RELU>(sm, O_H1, HS, 0, O_H2, HS, mw3, mb3);
    for (int i = tid; i < TS * COMP; i += FWD_THREADS) {
        int s = i / COMP, o = i - s * COMP;
        g_fout[(sbase + s) * COMP + o] = sm[O_H1 + s * HS + o];
    }
    layer_fwd<KS, CON, ACT_TANH>(sm, O_K1, 33, 0, O_X, XS, kw1, kb1);
    layer_fwd<16, KS, ACT_TANH>(sm, O_K2, 17, 0, O_K1, 33, kw2, kb2);
    if (tid < TS) {
        float z = kb3[0];
        #pragma unroll
        for (int i = 0; i < 16; i++) z = fmaf(sm[O_K2 + tid * 17 + i], kw3[i], z);
        g_kout[sbase + tid] = (z > 20.f) ? z : log1pf(expf(z));
    }
}

// =========================================================================
// Kernel 3: Jacobian norm + final output. 512 threads / 16 warps, 2 CTAs/SM
// (32 warps/SM, occ 50%). Scalar math, low register pressure:
//   GEMM1: 2x4 tiles (~240 tasks); trace: 4x4 symmetric, split-k=8.
// =========================================================================
#define SPC 4          // samples per CTA (sequential)
#define JT 512         // jac threads
#define JW 16          // jac warps

// smem layout (float offsets), stride 88
#define J_CW3   0                // CW3T: n2 x 88 (k-major). Gc overlays after GEMM1.
#define J_CW2   7744             // n2 x 88, pad cols exact 0
#define J_CB    15224            // Bc: 88 x 88
#define J_FROWS 22968            // SPC x 88
#define J_KOUT  23320            // SPC
#define J_MASKS 23324            // 24 unsigned
#define J_ACTL  23348            // SPC*3*88 ints
#define J_CNT   24404            // SPC*3 ints
#define J_WSUM  24416            // 16
#define JAC_SMEM_FLOATS 24432
#define JAC_SMEM_BYTES  (JAC_SMEM_FLOATS * 4)

__global__ __launch_bounds__(JT, 2)
void jac_kernel(const float* __restrict__ mw2, float* __restrict__ out)
{
    extern __shared__ float sm[];
    const int tid = threadIdx.x;
    const int wid = tid >> 5;
    const int lane = tid & 31;
    const int gs0 = blockIdx.x * SPC;
    unsigned* um = (unsigned*)(sm + J_MASKS);
    int* actl = (int*)(sm + J_ACTL);
    int* cnt = (int*)(sm + J_CNT);
    const uint32_t sb = (uint32_t)__cvta_generic_to_shared(sm);

    // ---- hoisted per-CTA setup ----
    for (int i = tid; i < SPC * COMP; i += JT) {
        int s = i / COMP, c = i - s * COMP;
        sm[J_FROWS + s * 88 + c] = g_fout[(gs0 + s) * COMP + c];
    }
    if (tid < SPC) sm[J_KOUT + tid] = g_kout[gs0 + tid];
    if (tid >= 32 && tid < 32 + SPC * 3) um[tid - 32] = g_d1m[gs0 * 3 + tid - 32];
    if (tid >= 64 && tid < 64 + SPC * 3) um[SPC * 3 + tid - 64] = g_d2m[gs0 * 3 + tid - 64];
    __syncthreads();

    // build all SPC*3 = 12 act lists: one per warp (warps 12-15 idle here)
    if (wid < SPC * 3) {
        int task = wid;   // 0..11
        int s = task / 3, L = task - 3 * s;
        int* act = actl + task * 88;
        int base = 0;
        for (int w = 0; w < 3; w++) {
            unsigned word;
            if (L == 0)      word = um[s * 3 + w];
            else if (L == 1) word = um[SPC * 3 + s * 3 + w];
            else {
                int idx = w * 32 + lane;
                word = __ballot_sync(0xFFFFFFFFu,
                                     idx < COMP && sm[J_FROWS + s * 88 + idx] > 0.f);
            }
            int idx = w * 32 + lane;
            if ((word >> lane) & 1u)
                act[base + __popc(word & ((1u << lane) - 1u))] = idx;
            base += __popc(word);
        }
        if (L != 1) {   // zero-pad act1/act3 so padded gathers stay in-bounds
            int np = (base + 3) & ~3;
            for (int p = base + lane; p < np; p += 32) act[p] = 0;
        }
        if (lane == 0) cnt[task] = base;
    }
    __syncthreads();

    // prologue: prefetch CW2 for sample 0
    {
        const int* act1 = actl + 0 * 88;
        const int* act2 = actl + 1 * 88;
        const int n1 = cnt[0], n2 = cnt[1];
        const int n1p = (n1 + 3) & ~3;
        for (int m = wid; m < n2; m += JW) {
            uint32_t d2 = sb + (J_CW2 + m * 88) * 4;
            const float* s2 = mw2 + act2[m] * COMP;
            for (int j = lane; j < n1p; j += 32) {
                if (j < n1) cpa4(d2 + j * 4, s2 + act1[j]);
                else sm[J_CW2 + m * 88 + j] = 0.f;
            }
        }
    }
    cpa_commit();

    // ---- per-sample loop ----
    for (int ss = 0; ss < SPC; ss++) {
        const int* act1 = actl + (ss * 3 + 0) * 88;
        const int* act2 = actl + (ss * 3 + 1) * 88;
        const int* act3 = actl + (ss * 3 + 2) * 88;
        const int n1 = cnt[ss * 3], n2 = cnt[ss * 3 + 1], n3 = cnt[ss * 3 + 2];
        const int n1p = (n1 + 3) & ~3;
        const int n3p = (n3 + 3) & ~3;
        const int nb1 = n1p >> 2;
        const int nr3 = n3p >> 1;      // 2-row GEMM1 tiles

        // P1: gather CW3T[m][i] = W3T[act2[m], act3[i]]  (sorted row gather)
        for (int m = wid; m < n2; m += JW) {
            uint32_t d3 = sb + (J_CW3 + m * 88) * 4;
            const float* s3 = g_W3T + act2[m] * COMP;
            for (int i = lane; i < n3p; i += 32)
                cpa4(d3 + i * 4, s3 + act3[i]);
        }
        cpa_commit();
        cpa_wait<0>();   // drains CW3T + this sample's CW2 prefetch
        __syncthreads();

        // P2: Bc[n3p x n1p] = W3c @ W2c (K = n2), 2x4 scalar tiles
        for (int t = tid; t < nr3 * nb1; t += JT) {
            int bi = t / nb1, bj = t - bi * nb1;
            int ii = bi << 1, jj = bj << 2;
            float a00=0,a01=0,a02=0,a03=0;
            float a10=0,a11=0,a12=0,a13=0;
            const float* w3t = sm + J_CW3 + ii;
            const float* w2 = sm + J_CW2 + jj;
            #pragma unroll 4
            for (int kk = 0; kk < n2; kk++) {
                float2 x = *(const float2*)(w3t + kk * 88);
                float4 b = *(const float4*)(w2 + kk * 88);
                a00 = fmaf(x.x, b.x, a00); a01 = fmaf(x.x, b.y, a01);
                a02 = fmaf(x.x, b.z, a02); a03 = fmaf(x.x, b.w, a03);
                a10 = fmaf(x.y, b.x, a10); a11 = fmaf(x.y, b.y, a11);
                a12 = fmaf(x.y, b.z, a12); a13 = fmaf(x.y, b.w, a13);
            }
            float* cb = sm + J_CB + ii * 88 + jj;
            *(float4*)(cb)      = make_float4(a00, a01, a02, a03);
            *(float4*)(cb + 88) = make_float4(a10, a11, a12, a13);
        }
        __syncthreads();

        // P3: Gc gather (group A) + next sample's CW2 prefetch (group B)
        float* gc = sm + J_CW3;
        for (int a = wid; a < n1; a += JW) {    // rows >= n1 stale: s==0 there
            const float* srow = g_G + act1[a] * COMP;
            uint32_t da = sb + (J_CW3 + a * 88) * 4;
            for (int b = lane; b < n1p; b += 32)
                cpa4(da + b * 4, srow + act1[b]);
        }
        cpa_commit();                            // group A
        if (ss + 1 < SPC) {
            const int* act1n = actl + ((ss + 1) * 3 + 0) * 88;
            const int* act2n = actl + ((ss + 1) * 3 + 1) * 88;
            const int n1n = cnt[(ss + 1) * 3], n2n = cnt[(ss + 1) * 3 + 1];
            const int n1pn = (n1n + 3) & ~3;
            for (int m = wid; m < n2n; m += JW) {
                uint32_t d2 = sb + (J_CW2 + m * 88) * 4;
                const float* s2 = mw2 + act2n[m] * COMP;
                for (int j = lane; j < n1pn; j += 32) {
                    if (j < n1n) cpa4(d2 + j * 4, s2 + act1n[j]);
                    else sm[J_CW2 + m * 88 + j] = 0.f;
                }
            }
        }
        cpa_commit();                            // group B (possibly empty)
        cpa_wait<1>();                           // A complete; B flies under trace
        __syncthreads();

        // P4: trace, symmetric 4x4 tiles, split-k=8 (linear in partial S).
        const int ntri = nb1 * (nb1 + 1) / 2;
        const int ntask = ntri << 3;
        float local = 0.f;
        for (int t = tid; t < ntask; t += JT) {
            int tile = t >> 3, part = t & 7;
            int bj = (int)((__fsqrt_rn(8.f * tile + 1.f) - 1.f) * 0.5f);
            while ((bj + 1) * (bj + 2) / 2 <= tile) bj++;
            while (bj * (bj + 1) / 2 > tile) bj--;
            int bi = tile - bj * (bj + 1) / 2;   // bi <= bj
            int aa = bi << 2, bb = bj << 2;
            int k0 = (n3 * part) >> 3;
            int k1 = (n3 * (part + 1)) >> 3;
            float s00=0,s01=0,s02=0,s03=0, s10=0,s11=0,s12=0,s13=0;
            float s20=0,s21=0,s22=0,s23=0, s30=0,s31=0,s32=0,s33=0;
            const float* ca = sm + J_CB + aa;
            const float* cbp = sm + J_CB + bb;
            for (int kk = k0; kk < k1; kk++) {
                float4 u = *(const float4*)(ca + kk * 88);
                float4 v = *(const float4*)(cbp + kk * 88);
                s00 = fmaf(u.x, v.x, s00); s01 = fmaf(u.x, v.y, s01);
                s02 = fmaf(u.x, v.z, s02); s03 = fmaf(u.x, v.w, s03);
                s10 = fmaf(u.y, v.x, s10); s11 = fmaf(u.y, v.y, s11);
                s12 = fmaf(u.y, v.z, s12); s13 = fmaf(u.y, v.w, s13);
                s20 = fmaf(u.z, v.x, s20); s21 = fmaf(u.z, v.y, s21);
                s22 = fmaf(u.z, v.z, s22); s23 = fmaf(u.z, v.w, s23);
                s30 = fmaf(u.w, v.x, s30); s31 = fmaf(u.w, v.y, s31);
                s32 = fmaf(u.w, v.z, s32); s33 = fmaf(u.w, v.w, s33);
            }
            float4 q0 = *(const float4*)(gc + (aa + 0) * 88 + bb);
            float4 q1 = *(const float4*)(gc + (aa + 1) * 88 + bb);
            float4 q2 = *(const float4*)(gc + (aa + 2) * 88 + bb);
            float4 q3 = *(const float4*)(gc + (aa + 3) * 88 + bb);
            if (bi < bj) {
                float p =
                      s00*q0.x + s01*q0.y + s02*q0.z + s03*q0.w
                    + s10*q1.x + s11*q1.y + s12*q1.z + s13*q1.w
                    + s20*q2.x + s21*q2.y + s22*q2.z + s23*q2.w
                    + s30*q3.x + s31*q3.y + s32*q3.z + s33*q3.w;
                local += 2.f * p;
            } else {
                // diagonal tile (aa == bb): weight c>r:2, c==r:1, c<r:0
                local += s00*q0.x + 2.f*(s01*q0.y + s02*q0.z + s03*q0.w)
                       + s11*q1.y + 2.f*(s12*q1.z + s13*q1.w)
                       + s22*q2.z + 2.f*(s23*q2.w)
                       + s33*q3.w;
            }
        }
        #pragma unroll
        for (int off = 16; off; off >>= 1)
            local += __shfl_down_sync(0xFFFFFFFFu, local, off);
        if (lane == 0) sm[J_WSUM + wid] = local;
        __syncthreads();

        // P5: output
        if (tid < COMP) {
            float ns = 0.f;
            #pragma unroll
            for (int w = 0; w < JW; w++) ns += sm[J_WSUM + w];
            float scal = 1.f / (sqrtf(ns) + 1e-4f);
            float kv = sm[J_KOUT + ss];
            out[(gs0 + ss) * COMP + tid] = tanhf(kv * sm[J_FROWS + ss * 88 + tid] * scal);
        }
        __syncthreads();
    }
}

// =========================================================================
// launch
// =========================================================================
extern "C" void kernel_launch(void* const* d_in, const int* in_sizes, int n_in,
                              void* d_out, int out_size)
{
    const float* obs    = (const float*)d_in[0];
    const float* action = (const float*)d_in[1];
    const float* ow1 = (const float*)d_in[2];
    const float* ob1 = (const float*)d_in[3];
    const float* ow2 = (const float*)d_in[4];
    const float* ob2 = (const float*)d_in[5];
    const float* aw1 = (const float*)d_in[6];
    const float* ab1 = (const float*)d_in[7];
    const float* aw2 = (const float*)d_in[8];
    const float* ab2 = (const float*)d_in[9];
    const float* mw1 = (const float*)d_in[10];
    const float* mb1 = (const float*)d_in[11];
    const float* mw2 = (const float*)d_in[12];
    const float* mb2 = (const float*)d_in[13];
    const float* mw3 = (const float*)d_in[14];
    const float* mb3 = (const float*)d_in[15];
    const float* kw1 = (const float*)d_in[16];
    const float* kb1 = (const float*)d_in[17];
    const float* kw2 = (const float*)d_in[18];
    const float* kb2 = (const float*)d_in[19];
    const float* kw3 = (const float*)d_in[20];
    const float* kb3 = (const float*)d_in[21];
    float* out = (float*)d_out;

    cudaFuncSetAttribute(fwd_kernel, cudaFuncAttributeMaxDynamicSharedMemorySize,
                         FWD_SMEM_BYTES);
    cudaFuncSetAttribute(jac_kernel, cudaFuncAttributeMaxDynamicSharedMemorySize,
                         JAC_SMEM_BYTES);

    g_kernel<<<(COMP * COMP * 32 + 255) / 256, 256>>>(mw1, mw3);
    fwd_kernel<<<BATCH / TS, FWD_THREADS, FWD_SMEM_BYTES>>>(
        obs, action, ow1, ob1, ow2, ob2, aw1, ab1, aw2, ab2,
        mw1, mb1, mw2, mb2, mw3, mb3, kw1, kb1, kw2, kb2, kw3, kb3);
    jac_kernel<<<BATCH / SPC, JT, JAC_SMEM_BYTES>>>(mw2, out);
}

// round 15
// speedup vs baseline: 1.1055x; 1.1055x over previous
#include <cuda_runtime.h>
#include <math.h>
#include <stdint.h>

// Problem dims
#define BATCH 8192
#define OBS 64
#define ACT 16
#define HID 128
#define CON 256
#define COMP 85
#define KS 32

// ---------------- scratch (device globals; no allocation) ----------------
__device__ float g_G[COMP * COMP];          // W1 W1^T
__device__ float g_W3T[COMP * COMP];        // mw3 transposed
__device__ float g_fout[BATCH * COMP];      // f-net output (relu(p3))
__device__ float g_kout[BATCH];             // k-net output (softplus)
__device__ unsigned g_d1m[BATCH * 3];       // d1 bitmask (85 bits in 3 words)
__device__ unsigned g_d2m[BATCH * 3];       // d2 bitmask

// ---- cp.async helpers ----
__device__ __forceinline__ void cpa4(uint32_t dst_smem, const float* src) {
    asm volatile("cp.async.ca.shared.global [%0], [%1], 4;"
                 :: "r"(dst_smem), "l"(src));
}
__device__ __forceinline__ void cpa_commit() {
    asm volatile("cp.async.commit_group;" ::: "memory");
}
template<int N>
__device__ __forceinline__ void cpa_wait() {
    asm volatile("cp.async.wait_group %0;" :: "n"(N) : "memory");
}

// ---- packed f32x2 helpers (sm_100a; exact dual fp32 FMA) ----
__device__ __forceinline__ unsigned long long pack2_dup(float x) {
    unsigned long long r;
    uint32_t u = __float_as_uint(x);
    asm("mov.b64 %0, {%1, %2};" : "=l"(r) : "r"(u), "r"(u));
    return r;
}
__device__ __forceinline__ unsigned long long fma2(
    unsigned long long a, unsigned long long b, unsigned long long c) {
    unsigned long long d;
    asm("fma.rn.f32x2 %0, %1, %2, %3;" : "=l"(d) : "l"(a), "l"(b), "l"(c));
    return d;
}
__device__ __forceinline__ void lds_v2u64(uint32_t addr,
                                          unsigned long long& a,
                                          unsigned long long& b) {
    asm volatile("ld.shared.v2.b64 {%0, %1}, [%2];"
                 : "=l"(a), "=l"(b) : "r"(addr));
}
__device__ __forceinline__ void sts_v2u64(uint32_t addr,
                                          unsigned long long a,
                                          unsigned long long b) {
    asm volatile("st.shared.v2.b64 [%0], {%1, %2};"
                 :: "r"(addr), "l"(a), "l"(b) : "memory");
}
__device__ __forceinline__ void unpack2(unsigned long long v, float& lo, float& hi) {
    uint32_t l, h;
    asm("mov.b64 {%0, %1}, %2;" : "=r"(l), "=r"(h) : "l"(v));
    lo = __uint_as_float(l);
    hi = __uint_as_float(h);
}

// =========================================================================
// Kernel 1: G = mw1 @ mw1^T (warp per element) + W3 transpose
// =========================================================================
__global__ __launch_bounds__(256)
void g_kernel(const float* __restrict__ mw1, const float* __restrict__ mw3) {
    int gid = blockIdx.x * 256 + threadIdx.x;
    if (gid < COMP * COMP) {
        int r = gid / COMP, c = gid - r * COMP;
        g_W3T[c * COMP + r] = mw3[gid];
    }
    int gw = gid >> 5;   // global warp id
    int lane = threadIdx.x & 31;
    if (gw >= COMP * COMP) return;
    int i = gw / COMP;
    int j = gw - i * COMP;
    const float4* a = (const float4*)(mw1 + i * CON);
    const float4* b = (const float4*)(mw1 + j * CON);
    float acc = 0.f;
    #pragma unroll
    for (int t = 0; t < 2; t++) {
        float4 av = a[lane + 32 * t];
        float4 bv = b[lane + 32 * t];
        acc += av.x * bv.x + av.y * bv.y + av.z * bv.z + av.w * bv.w;
    }
    #pragma unroll
    for (int off = 16; off; off >>= 1)
        acc += __shfl_down_sync(0xFFFFFFFFu, acc, off);
    if (lane == 0) g_G[gw] = acc;
}

// =========================================================================
// Kernel 2: fused forward pass. 64 samples per CTA, 1024 threads.
// Thread map: sp = tid>>5 (0..31) owns samples {2sp, 2sp+1}; q = tid&31
// owns output cols o = q + 32j. 32 warps/SM (1 CTA/SM).
// =========================================================================
#define TS 64
#define FWD_THREADS 1024

// smem layout (float offsets)
#define O_X   0            // x buffer 64 x 257 (concat of/af)
#define XS    257
#define O_W   16448        // weight staging 16512 floats
#define O_T   32960        // head layer-1 temp 64 x 129
#define TBS   129
#define O_IN  41216        // input staging 64 x 65 (also k1/k2 bufs)
#define O_K1  41216        // k1: 64 x 33
#define O_K2  43328        // k2: 64 x 17
#define O_H1  45376        // h1 / f_out: 64 x 87
#define O_H2  50944        // h2: 64 x 87
#define HS    87
#define FWD_SMEM_FLOATS 56512
#define FWD_SMEM_BYTES  (FWD_SMEM_FLOATS * 4)

#define ACT_RELU 0
#define ACT_TANH 1

template<int N, int K, int ACTT>
__device__ __forceinline__ void layer_fwd(
    float* __restrict__ sm,
    int o_out, int outStride, int outColOff,
    int o_in, int inStride,
    const float* __restrict__ Wg, const float* __restrict__ bg)
{
    constexpr int NJ = (N + 31) / 32;
    const int tid = threadIdx.x;
    const int sp = tid >> 5;       // 0..31, samples 2sp, 2sp+1
    const int q = tid & 31;        // output col group

    float acc[2][NJ];
    #pragma unroll
    for (int s = 0; s < 2; s++)
        #pragma unroll
        for (int j = 0; j < NJ; j++) acc[s][j] = 0.f;

    float* wbuf = sm + O_W;
    constexpr int KC = (K > 128) ? 128 : K;
    constexpr int WS = KC | 1;     // odd stride -> conflict-free weight columns

    #pragma unroll
    for (int k0 = 0; k0 < K; k0 += KC) {
        __syncthreads();
        {
            constexpr int TOT = N * KC;
            constexpr int NIT = (TOT + FWD_THREADS - 1) / FWD_THREADS;
            int i = tid;
            #pragma unroll
            for (int u = 0; u < NIT; u++) {
                if (i < TOT) {
                    int r = i / KC;
                    int c = i - r * KC;
                    wbuf[r * WS + c] = Wg[r * K + k0 + c];
                }
                i += FWD_THREADS;
            }
        }
        __syncthreads();
        const float* in0 = sm + o_in + (2 * sp + 0) * inStride + k0;
        const float* in1 = sm + o_in + (2 * sp + 1) * inStride + k0;
        #pragma unroll 2
        for (int k = 0; k < KC; k++) {
            float a0 = in0[k], a1 = in1[k];
            const float* wr = wbuf + k + q * WS;
            #pragma unroll
            for (int j = 0; j < NJ; j++) {
                float w = wr[(j << 5) * WS];
                acc[0][j] = fmaf(a0, w, acc[0][j]);
                acc[1][j] = fmaf(a1, w, acc[1][j]);
            }
        }
    }
    #pragma unroll
    for (int j = 0; j < NJ; j++) {
        int o = q + (j << 5);
        if (o < N) {
            float bv = bg[o];
            #pragma unroll
            for (int s = 0; s < 2; s++) {
                float v = acc[s][j] + bv;
                if (ACTT == ACT_RELU) v = fmaxf(v, 0.f);
                else if (ACTT == ACT_TANH) v = tanhf(v);
                sm[o_out + (2 * sp + s) * outStride + outColOff + o] = v;
            }
        }
    }
    __syncthreads();
}

__global__ __launch_bounds__(FWD_THREADS)
void fwd_kernel(
    const float* __restrict__ obs, const float* __restrict__ action,
    const float* __restrict__ ow1, const float* __restrict__ ob1,
    const float* __restrict__ ow2, const float* __restrict__ ob2,
    const float* __restrict__ aw1, const float* __restrict__ ab1,
    const float* __restrict__ aw2, const float* __restrict__ ab2,
    const float* __restrict__ mw1, const float* __restrict__ mb1,
    const float* __restrict__ mw2, const float* __restrict__ mb2,
    const float* __restrict__ mw3, const float* __restrict__ mb3,
    const float* __restrict__ kw1, const float* __restrict__ kb1,
    const float* __restrict__ kw2, const float* __restrict__ kb2,
    const float* __restrict__ kw3, const float* __restrict__ kb3)
{
    extern __shared__ float sm[];
    const int tid = threadIdx.x;
    const int sbase = blockIdx.x * TS;

    for (int i = tid; i < TS * OBS; i += FWD_THREADS) {
        int s = i >> 6, k = i & 63;
        sm[O_IN + s * 65 + k] = obs[(sbase + s) * OBS + k];
    }
    __syncthreads();
    layer_fwd<HID, OBS, ACT_RELU>(sm, O_T, TBS, 0, O_IN, 65, ow1, ob1);
    layer_fwd<HID, HID, ACT_RELU>(sm, O_X, XS, 0, O_T, TBS, ow2, ob2);

    for (int i = tid; i < TS * ACT; i += FWD_THREADS) {
        int s = i >> 4, k = i & 15;
        sm[O_IN + s * 17 + k] = action[(sbase + s) * ACT + k];
    }
    __syncthreads();
    layer_fwd<HID, ACT, ACT_RELU>(sm, O_T, TBS, 0, O_IN, 17, aw1, ab1);
    layer_fwd<HID, HID, ACT_RELU>(sm, O_X, XS, 128, O_T, TBS, aw2, ab2);

    layer_fwd<COMP, CON, ACT_RELU>(sm, O_H1, HS, 0, O_X, XS, mw1, mb1);
    if (tid < TS * 3) {
        int s = tid / 3, w = tid - 3 * s;
        unsigned m = 0;
        for (int b = 0; b < 32; b++) {
            int idx = w * 32 + b;
            if (idx < COMP && sm[O_H1 + s * HS + idx] > 0.f) m |= 1u << b;
        }
        g_d1m[(sbase + s) * 3 + w] = m;
    }
    layer_fwd<COMP, COMP, ACT_RELU>(sm, O_H2, HS, 0, O_H1, HS, mw2, mb2);
    if (tid < TS * 3) {
        int s = tid / 3, w = tid - 3 * s;
        unsigned m = 0;
        for (int b = 0; b < 32; b++) {
            int idx = w * 32 + b;
            if (idx < COMP && sm[O_H2 + s * HS + idx] > 0.f) m |= 1u << b;
        }
        g_d2m[(sbase + s) * 3 + w] = m;
    }
    layer_fwd<COMP, COMP, ACT_RELU>(sm, O_H1, HS, 0, O_H2, HS, mw3, mb3);
    for (int i = tid; i < TS * COMP; i += FWD_THREADS) {
        int s = i / COMP, o = i - s * COMP;
        g_fout[(sbase + s) * COMP + o] = sm[O_H1 + s * HS + o];
    }
    layer_fwd<KS, CON, ACT_TANH>(sm, O_K1, 33, 0, O_X, XS, kw1, kb1);
    layer_fwd<16, KS, ACT_TANH>(sm, O_K2, 17, 0, O_K1, 33, kw2, kb2);
    if (tid < TS) {
        float z = kb3[0];
        #pragma unroll
        for (int i = 0; i < 16; i++) z = fmaf(sm[O_K2 + tid * 17 + i], kw3[i], z);
        g_kout[sbase + tid] = (z > 20.f) ? z : log1pf(expf(z));
    }
}

// =========================================================================
// Kernel 3: Jacobian norm + final output. EXACT R12 config (best known):
// 384 threads / 12 warps, 2 CTAs/SM, f32x2 GEMM1 4x4, split-k=4 trace.
// =========================================================================
#define SPC 4          // samples per CTA (sequential)
#define JT 384         // jac threads
#define JW 12          // jac warps

// smem layout (float offsets), stride 88
#define J_CW3   0                // CW3T: n2 x 88 (k-major). Gc overlays after GEMM1.
#define J_CW2   7744             // n2 x 88, pad cols exact 0
#define J_CB    15224            // Bc: 88 x 88
#define J_FROWS 22968            // SPC x 88
#define J_KOUT  23320            // SPC
#define J_MASKS 23324            // 24 unsigned
#define J_ACTL  23348            // SPC*3*88 ints
#define J_CNT   24404            // SPC*3 ints
#define J_WSUM  24416            // 12
#define JAC_SMEM_FLOATS 24432
#define JAC_SMEM_BYTES  (JAC_SMEM_FLOATS * 4)

__global__ __launch_bounds__(JT, 2)
void jac_kernel(const float* __restrict__ mw2, float* __restrict__ out)
{
    extern __shared__ float sm[];
    const int tid = threadIdx.x;
    const int wid = tid >> 5;
    const int lane = tid & 31;
    const int gs0 = blockIdx.x * SPC;
    unsigned* um = (unsigned*)(sm + J_MASKS);
    int* actl = (int*)(sm + J_ACTL);
    int* cnt = (int*)(sm + J_CNT);
    const uint32_t sb = (uint32_t)__cvta_generic_to_shared(sm);

    // ---- hoisted per-CTA setup ----
    for (int i = tid; i < SPC * COMP; i += JT) {
        int s = i / COMP, c = i - s * COMP;
        sm[J_FROWS + s * 88 + c] = g_fout[(gs0 + s) * COMP + c];
    }
    if (tid < SPC) sm[J_KOUT + tid] = g_kout[gs0 + tid];
    if (tid >= 32 && tid < 32 + SPC * 3) um[tid - 32] = g_d1m[gs0 * 3 + tid - 32];
    if (tid >= 64 && tid < 64 + SPC * 3) um[SPC * 3 + tid - 64] = g_d2m[gs0 * 3 + tid - 64];
    __syncthreads();

    // build all SPC*3 = 12 act lists: exactly one per warp
    {
        int task = wid;   // 0..11
        int s = task / 3, L = task - 3 * s;
        int* act = actl + task * 88;
        int base = 0;
        for (int w = 0; w < 3; w++) {
            unsigned word;
            if (L == 0)      word = um[s * 3 + w];
            else if (L == 1) word = um[SPC * 3 + s * 3 + w];
            else {
                int idx = w * 32 + lane;
                word = __ballot_sync(0xFFFFFFFFu,
                                     idx < COMP && sm[J_FROWS + s * 88 + idx] > 0.f);
            }
            int idx = w * 32 + lane;
            if ((word >> lane) & 1u)
                act[base + __popc(word & ((1u << lane) - 1u))] = idx;
            base += __popc(word);
        }
        if (L != 1) {   // zero-pad act1/act3 so padded gathers stay in-bounds
            int np = (base + 3) & ~3;
            for (int p = base + lane; p < np; p += 32) act[p] = 0;
        }
        if (lane == 0) cnt[task] = base;
    }
    __syncthreads();

    // prologue: prefetch CW2 for sample 0
    {
        const int* act1 = actl + 0 * 88;
        const int* act2 = actl + 1 * 88;
        const int n1 = cnt[0], n2 = cnt[1];
        const int n1p = (n1 + 3) & ~3;
        for (int m = wid; m < n2; m += JW) {
            uint32_t d2 = sb + (J_CW2 + m * 88) * 4;
            const float* s2 = mw2 + act2[m] * COMP;
            for (int j = lane; j < n1p; j += 32) {
                if (j < n1) cpa4(d2 + j * 4, s2 + act1[j]);
                else sm[J_CW2 + m * 88 + j] = 0.f;
            }
        }
    }
    cpa_commit();

    // ---- per-sample loop ----
    for (int ss = 0; ss < SPC; ss++) {
        const int* act1 = actl + (ss * 3 + 0) * 88;
        const int* act2 = actl + (ss * 3 + 1) * 88;
        const int* act3 = actl + (ss * 3 + 2) * 88;
        const int n1 = cnt[ss * 3], n2 = cnt[ss * 3 + 1], n3 = cnt[ss * 3 + 2];
        const int n1p = (n1 + 3) & ~3;
        const int n3p = (n3 + 3) & ~3;
        const int nb1 = n1p >> 2, nb3 = n3p >> 2;

        // P1: gather CW3T[m][i] = W3T[act2[m], act3[i]]  (sorted row gather)
        for (int m = wid; m < n2; m += JW) {
            uint32_t d3 = sb + (J_CW3 + m * 88) * 4;
            const float* s3 = g_W3T + act2[m] * COMP;
            for (int i = lane; i < n3p; i += 32)
                cpa4(d3 + i * 4, s3 + act3[i]);
        }
        cpa_commit();
        cpa_wait<0>();   // drains CW3T + this sample's CW2 prefetch
        __syncthreads();

        // P2: Bc[n3p x n1p] = W3c @ W2c (K = n2), 4x4 tiles, f32x2 FMAs
        for (int t = tid; t < nb3 * nb1; t += JT) {
            int bi = t / nb1, bj = t - bi * nb1;
            int ii = bi << 2, jj = bj << 2;
            unsigned long long a0l=0,a0h=0, a1l=0,a1h=0;
            unsigned long long a2l=0,a2h=0, a3l=0,a3h=0;
            const float* w3t = sm + J_CW3 + ii;
            uint32_t w2a = sb + (J_CW2 + jj) * 4;
            #pragma unroll 4
            for (int kk = 0; kk < n2; kk++) {
                float4 x = *(const float4*)(w3t + kk * 88);
                unsigned long long b01, b23;
                lds_v2u64(w2a + kk * 352, b01, b23);
                unsigned long long x0 = pack2_dup(x.x);
                unsigned long long x1 = pack2_dup(x.y);
                unsigned long long x2 = pack2_dup(x.z);
                unsigned long long x3 = pack2_dup(x.w);
                a0l = fma2(x0, b01, a0l); a0h = fma2(x0, b23, a0h);
                a1l = fma2(x1, b01, a1l); a1h = fma2(x1, b23, a1h);
                a2l = fma2(x2, b01, a2l); a2h = fma2(x2, b23, a2h);
                a3l = fma2(x3, b01, a3l); a3h = fma2(x3, b23, a3h);
            }
            uint32_t cba = sb + (J_CB + ii * 88 + jj) * 4;
            sts_v2u64(cba,        a0l, a0h);
            sts_v2u64(cba + 352,  a1l, a1h);
            sts_v2u64(cba + 704,  a2l, a2h);
            sts_v2u64(cba + 1056, a3l, a3h);
        }
        __syncthreads();

        // P3: Gc gather (group A) + next sample's CW2 prefetch (group B)
        float* gc = sm + J_CW3;
        for (int a = wid; a < n1; a += JW) {    // rows >= n1 stale: s==0 there
            const float* srow = g_G + act1[a] * COMP;
            uint32_t da = sb + (J_CW3 + a * 88) * 4;
            for (int b = lane; b < n1p; b += 32)
                cpa4(da + b * 4, srow + act1[b]);
        }
        cpa_commit();                            // group A
        if (ss + 1 < SPC) {
            const int* act1n = actl + ((ss + 1) * 3 + 0) * 88;
            const int* act2n = actl + ((ss + 1) * 3 + 1) * 88;
            const int n1n = cnt[(ss + 1) * 3], n2n = cnt[(ss + 1) * 3 + 1];
            const int n1pn = (n1n + 3) & ~3;
            for (int m = wid; m < n2n; m += JW) {
                uint32_t d2 = sb + (J_CW2 + m * 88) * 4;
                const float* s2 = mw2 + act2n[m] * COMP;
                for (int j = lane; j < n1pn; j += 32) {
                    if (j < n1n) cpa4(d2 + j * 4, s2 + act1n[j]);
                    else sm[J_CW2 + m * 88 + j] = 0.f;
                }
            }
        }
        cpa_commit();                            // group B (possibly empty)
        cpa_wait<1>();                           // A complete; B flies under trace
        __syncthreads();

        // P4: trace, symmetric 4x4 tiles, split-k=4 (linear in partial S).
        const int ntri = nb1 * (nb1 + 1) / 2;
        const int ntask = ntri << 2;
        float local = 0.f;
        for (int t = tid; t < ntask; t += JT) {
            int tile = t >> 2, part = t & 3;
            int bj = (int)((__fsqrt_rn(8.f * tile + 1.f) - 1.f) * 0.5f);
            while ((bj + 1) * (bj + 2) / 2 <= tile) bj++;
            while (bj * (bj + 1) / 2 > tile) bj--;
            int bi = tile - bj * (bj + 1) / 2;   // bi <= bj
            int aa = bi << 2, bb = bj << 2;
            int k0 = (n3 * part) >> 2;
            int k1 = (n3 * (part + 1)) >> 2;
            unsigned long long s0l=0,s0h=0, s1l=0,s1h=0;
            unsigned long long s2l=0,s2h=0, s3l=0,s3h=0;
            const float* ca = sm + J_CB + aa;
            uint32_t vb = sb + (J_CB + bb) * 4;
            #pragma unroll 4
            for (int kk = k0; kk < k1; kk++) {
                float4 u = *(const float4*)(ca + kk * 88);
                unsigned long long v01, v23;
                lds_v2u64(vb + kk * 352, v01, v23);
                unsigned long long u0 = pack2_dup(u.x);
                unsigned long long u1 = pack2_dup(u.y);
                unsigned long long u2 = pack2_dup(u.z);
                unsigned long long u3 = pack2_dup(u.w);
                s0l = fma2(u0, v01, s0l); s0h = fma2(u0, v23, s0h);
                s1l = fma2(u1, v01, s1l); s1h = fma2(u1, v23, s1h);
                s2l = fma2(u2, v01, s2l); s2h = fma2(u2, v23, s2h);
                s3l = fma2(u3, v01, s3l); s3h = fma2(u3, v23, s3h);
            }
            float s00,s01,s02,s03, s10,s11,s12,s13;
            float s20,s21,s22,s23, s30,s31,s32,s33;
            unpack2(s0l, s00, s01); unpack2(s0h, s02, s03);
            unpack2(s1l, s10, s11); unpack2(s1h, s12, s13);
            unpack2(s2l, s20, s21); unpack2(s2h, s22, s23);
            unpack2(s3l, s30, s31); unpack2(s3h, s32, s33);
            float4 q0 = *(const float4*)(gc + (aa + 0) * 88 + bb);
            float4 q1 = *(const float4*)(gc + (aa + 1) * 88 + bb);
            float4 q2 = *(const float4*)(gc + (aa + 2) * 88 + bb);
            float4 q3 = *(const float4*)(gc + (aa + 3) * 88 + bb);
            if (bi < bj) {
                float p =
                      s00*q0.x + s01*q0.y + s02*q0.z + s03*q0.w
                    + s10*q1.x + s11*q1.y + s12*q1.z + s13*q1.w
                    + s20*q2.x + s21*q2.y + s22*q2.z + s23*q2.w
                    + s30*q3.x + s31*q3.y + s32*q3.z + s33*q3.w;
                local += 2.f * p;
            } else {
                // diagonal tile (aa == bb): weight c>r:2, c==r:1, c<r:0
                local += s00*q0.x + 2.f*(s01*q0.y + s02*q0.z + s03*q0.w)
                       + s11*q1.y + 2.f*(s12*q1.z + s13*q1.w)
                       + s22*q2.z + 2.f*(s23*q2.w)
                       + s33*q3.w;
            }
        }
        #pragma unroll
        for (int off = 16; off; off >>= 1)
            local += __shfl_down_sync(0xFFFFFFFFu, local, off);
        if (lane == 0) sm[J_WSUM + wid] = local;
        __syncthreads();

        // P5: output
        if (tid < COMP) {
            float ns = 0.f;
            #pragma unroll
            for (int w = 0; w < JW; w++) ns += sm[J_WSUM + w];
            float scal = 1.f / (sqrtf(ns) + 1e-4f);
            float kv = sm[J_KOUT + ss];
            out[(gs0 + ss) * COMP + tid] = tanhf(kv * sm[J_FROWS + ss * 88 + tid] * scal);
        }
        __syncthreads();
    }
}

// =========================================================================
// launch
// =========================================================================
extern "C" void kernel_launch(void* const* d_in, const int* in_sizes, int n_in,
                              void* d_out, int out_size)
{
    const float* obs    = (const float*)d_in[0];
    const float* action = (const float*)d_in[1];
    const float* ow1 = (const float*)d_in[2];
    const float* ob1 = (const float*)d_in[3];
    const float* ow2 = (const float*)d_in[4];
    const float* ob2 = (const float*)d_in[5];
    const float* aw1 = (const float*)d_in[6];
    const float* ab1 = (const float*)d_in[7];
    const float* aw2 = (const float*)d_in[8];
    const float* ab2 = (const float*)d_in[9];
    const float* mw1 = (const float*)d_in[10];
    const float* mb1 = (const float*)d_in[11];
    const float* mw2 = (const float*)d_in[12];
    const float* mb2 = (const float*)d_in[13];
    const float* mw3 = (const float*)d_in[14];
    const float* mb3 = (const float*)d_in[15];
    const float* kw1 = (const float*)d_in[16];
    const float* kb1 = (const float*)d_in[17];
    const float* kw2 = (const float*)d_in[18];
    const float* kb2 = (const float*)d_in[19];
    const float* kw3 = (const float*)d_in[20];
    const float* kb3 = (const float*)d_in[21];
    float* out = (float*)d_out;

    cudaFuncSetAttribute(fwd_kernel, cudaFuncAttributeMaxDynamicSharedMemorySize,
                         FWD_SMEM_BYTES);
    cudaFuncSetAttribute(jac_kernel, cudaFuncAttributeMaxDynamicSharedMemorySize,
                         JAC_SMEM_BYTES);

    g_kernel<<<(COMP * COMP * 32 + 255) / 256, 256>>>(mw1, mw3);
    fwd_kernel<<<BATCH / TS, FWD_THREADS, FWD_SMEM_BYTES>>>(
        obs, action, ow1, ob1, ow2, ob2, aw1, ab1, aw2, ab2,
        mw1, mb1, mw2, mb2, mw3, mb3, kw1, kb1, kw2, kb2, kw3, kb3);
    jac_kernel<<<BATCH / SPC, JT, JAC_SMEM_BYTES>>>(mw2, out);
}

// round 16
// speedup vs baseline: 1.1826x; 1.0698x over previous
#include <cuda_runtime.h>
#include <math.h>
#include <stdint.h>

// Problem dims
#define BATCH 8192
#define OBS 64
#define ACT 16
#define HID 128
#define CON 256
#define COMP 85
#define KS 32

// ---------------- scratch (device globals; no allocation) ----------------
__device__ float g_G[COMP * COMP];          // W1 W1^T
__device__ float g_W3T[COMP * COMP];        // mw3 transposed
__device__ float g_fout[BATCH * COMP];      // f-net output (relu(p3))
__device__ float g_kout[BATCH];             // k-net output (softplus)
__device__ unsigned g_d1m[BATCH * 3];       // d1 bitmask (85 bits in 3 words)
__device__ unsigned g_d2m[BATCH * 3];       // d2 bitmask

// ---- cp.async helpers ----
__device__ __forceinline__ void cpa4(uint32_t dst_smem, const float* src) {
    asm volatile("cp.async.ca.shared.global [%0], [%1], 4;"
                 :: "r"(dst_smem), "l"(src));
}
__device__ __forceinline__ void cpa_commit() {
    asm volatile("cp.async.commit_group;" ::: "memory");
}
template<int N>
__device__ __forceinline__ void cpa_wait() {
    asm volatile("cp.async.wait_group %0;" :: "n"(N) : "memory");
}

// ---- packed f32x2 helpers (sm_100a; exact dual fp32 FMA) ----
__device__ __forceinline__ unsigned long long pack2_dup(float x) {
    unsigned long long r;
    uint32_t u = __float_as_uint(x);
    asm("mov.b64 %0, {%1, %2};" : "=l"(r) : "r"(u), "r"(u));
    return r;
}
__device__ __forceinline__ unsigned long long fma2(
    unsigned long long a, unsigned long long b, unsigned long long c) {
    unsigned long long d;
    asm("fma.rn.f32x2 %0, %1, %2, %3;" : "=l"(d) : "l"(a), "l"(b), "l"(c));
    return d;
}
__device__ __forceinline__ void lds_v2u64(uint32_t addr,
                                          unsigned long long& a,
                                          unsigned long long& b) {
    asm volatile("ld.shared.v2.b64 {%0, %1}, [%2];"
                 : "=l"(a), "=l"(b) : "r"(addr));
}
__device__ __forceinline__ void sts_v2u64(uint32_t addr,
                                          unsigned long long a,
                                          unsigned long long b) {
    asm volatile("st.shared.v2.b64 [%0], {%1, %2};"
                 :: "r"(addr), "l"(a), "l"(b) : "memory");
}
__device__ __forceinline__ void unpack2(unsigned long long v, float& lo, float& hi) {
    uint32_t l, h;
    asm("mov.b64 {%0, %1}, %2;" : "=r"(l), "=r"(h) : "l"(v));
    lo = __uint_as_float(l);
    hi = __uint_as_float(h);
}

// =========================================================================
// Kernel 1: G = mw1 @ mw1^T (warp per element) + W3 transpose
// =========================================================================
__global__ __launch_bounds__(256)
void g_kernel(const float* __restrict__ mw1, const float* __restrict__ mw3) {
    int gid = blockIdx.x * 256 + threadIdx.x;
    if (gid < COMP * COMP) {
        int r = gid / COMP, c = gid - r * COMP;
        g_W3T[c * COMP + r] = mw3[gid];
    }
    int gw = gid >> 5;   // global warp id
    int lane = threadIdx.x & 31;
    if (gw >= COMP * COMP) return;
    int i = gw / COMP;
    int j = gw - i * COMP;
    const float4* a = (const float4*)(mw1 + i * CON);
    const float4* b = (const float4*)(mw1 + j * CON);
    float acc = 0.f;
    #pragma unroll
    for (int t = 0; t < 2; t++) {
        float4 av = a[lane + 32 * t];
        float4 bv = b[lane + 32 * t];
        acc += av.x * bv.x + av.y * bv.y + av.z * bv.z + av.w * bv.w;
    }
    #pragma unroll
    for (int off = 16; off; off >>= 1)
        acc += __shfl_down_sync(0xFFFFFFFFu, acc, off);
    if (lane == 0) g_G[gw] = acc;
}

// =========================================================================
// Kernel 2: fused forward pass. 64 samples per CTA, 512 threads,
// 4 samples per 32-thread group (R12 config — best known).
// =========================================================================
#define TS 64
#define FWD_THREADS 512

// smem layout (float offsets)
#define O_X   0            // x buffer 64 x 257 (concat of/af)
#define XS    257
#define O_W   16448        // weight staging 16512 floats
#define O_T   32960        // head layer-1 temp 64 x 129
#define TBS   129
#define O_IN  41216        // input staging 64 x 65 (also k1/k2 bufs)
#define O_K1  41216        // k1: 64 x 33
#define O_K2  43328        // k2: 64 x 17
#define O_H1  45376        // h1 / f_out: 64 x 87
#define O_H2  50944        // h2: 64 x 87
#define HS    87
#define FWD_SMEM_FLOATS 56512
#define FWD_SMEM_BYTES  (FWD_SMEM_FLOATS * 4)

#define ACT_RELU 0
#define ACT_TANH 1

template<int N, int K, int ACTT>
__device__ __forceinline__ void layer_fwd(
    float* __restrict__ sm,
    int o_out, int outStride, int outColOff,
    int o_in, int inStride,
    const float* __restrict__ Wg, const float* __restrict__ bg)
{
    constexpr int NJ = (N + 31) / 32;
    const int tid = threadIdx.x;
    const int sp = tid >> 5;       // 0..15, samples 4sp..4sp+3
    const int q = tid & 31;        // output col group

    float acc[4][NJ];
    #pragma unroll
    for (int s = 0; s < 4; s++)
        #pragma unroll
        for (int j = 0; j < NJ; j++) acc[s][j] = 0.f;

    float* wbuf = sm + O_W;
    constexpr int KC = (K > 128) ? 128 : K;
    constexpr int WS = KC | 1;     // odd stride -> conflict-free weight columns

    #pragma unroll
    for (int k0 = 0; k0 < K; k0 += KC) {
        __syncthreads();
        {
            constexpr int TOT = N * KC;
            constexpr int NIT = (TOT + FWD_THREADS - 1) / FWD_THREADS;
            int i = tid;
            #pragma unroll
            for (int u = 0; u < NIT; u++) {
                if (i < TOT) {
                    int r = i / KC;
                    int c = i - r * KC;
                    wbuf[r * WS + c] = Wg[r * K + k0 + c];
                }
                i += FWD_THREADS;
            }
        }
        __syncthreads();
        const float* in0 = sm + o_in + (4 * sp + 0) * inStride + k0;
        const float* in1 = sm + o_in + (4 * sp + 1) * inStride + k0;
        const float* in2 = sm + o_in + (4 * sp + 2) * inStride + k0;
        const float* in3 = sm + o_in + (4 * sp + 3) * inStride + k0;
        #pragma unroll 2
        for (int k = 0; k < KC; k++) {
            float a0 = in0[k], a1 = in1[k], a2 = in2[k], a3 = in3[k];
            const float* wr = wbuf + k + q * WS;
            #pragma unroll
            for (int j = 0; j < NJ; j++) {
                float w = wr[(j << 5) * WS];
                acc[0][j] = fmaf(a0, w, acc[0][j]);
                acc[1][j] = fmaf(a1, w, acc[1][j]);
                acc[2][j] = fmaf(a2, w, acc[2][j]);
                acc[3][j] = fmaf(a3, w, acc[3][j]);
            }
        }
    }
    #pragma unroll
    for (int j = 0; j < NJ; j++) {
        int o = q + (j << 5);
        if (o < N) {
            float bv = bg[o];
            #pragma unroll
            for (int s = 0; s < 4; s++) {
                float v = acc[s][j] + bv;
                if (ACTT == ACT_RELU) v = fmaxf(v, 0.f);
                else if (ACTT == ACT_TANH) v = tanhf(v);
                sm[o_out + (4 * sp + s) * outStride + outColOff + o] = v;
            }
        }
    }
    __syncthreads();
}

__global__ __launch_bounds__(FWD_THREADS)
void fwd_kernel(
    const float* __restrict__ obs, const float* __restrict__ action,
    const float* __restrict__ ow1, const float* __restrict__ ob1,
    const float* __restrict__ ow2, const float* __restrict__ ob2,
    const float* __restrict__ aw1, const float* __restrict__ ab1,
    const float* __restrict__ aw2, const float* __restrict__ ab2,
    const float* __restrict__ mw1, const float* __restrict__ mb1,
    const float* __restrict__ mw2, const float* __restrict__ mb2,
    const float* __restrict__ mw3, const float* __restrict__ mb3,
    const float* __restrict__ kw1, const float* __restrict__ kb1,
    const float* __restrict__ kw2, const float* __restrict__ kb2,
    const float* __restrict__ kw3, const float* __restrict__ kb3)
{
    extern __shared__ float sm[];
    const int tid = threadIdx.x;
    const int sbase = blockIdx.x * TS;

    for (int i = tid; i < TS * OBS; i += FWD_THREADS) {
        int s = i >> 6, k = i & 63;
        sm[O_IN + s * 65 + k] = obs[(sbase + s) * OBS + k];
    }
    __syncthreads();
    layer_fwd<HID, OBS, ACT_RELU>(sm, O_T, TBS, 0, O_IN, 65, ow1, ob1);
    layer_fwd<HID, HID, ACT_RELU>(sm, O_X, XS, 0, O_T, TBS, ow2, ob2);

    for (int i = tid; i < TS * ACT; i += FWD_THREADS) {
        int s = i >> 4, k = i & 15;
        sm[O_IN + s * 17 + k] = action[(sbase + s) * ACT + k];
    }
    __syncthreads();
    layer_fwd<HID, ACT, ACT_RELU>(sm, O_T, TBS, 0, O_IN, 17, aw1, ab1);
    layer_fwd<HID, HID, ACT_RELU>(sm, O_X, XS, 128, O_T, TBS, aw2, ab2);

    layer_fwd<COMP, CON, ACT_RELU>(sm, O_H1, HS, 0, O_X, XS, mw1, mb1);
    if (tid < TS * 3) {
        int s = tid / 3, w = tid - 3 * s;
        unsigned m = 0;
        for (int b = 0; b < 32; b++) {
            int idx = w * 32 + b;
            if (idx < COMP && sm[O_H1 + s * HS + idx] > 0.f) m |= 1u << b;
        }
        g_d1m[(sbase + s) * 3 + w] = m;
    }
    layer_fwd<COMP, COMP, ACT_RELU>(sm, O_H2, HS, 0, O_H1, HS, mw2, mb2);
    if (tid < TS * 3) {
        int s = tid / 3, w = tid - 3 * s;
        unsigned m = 0;
        for (int b = 0; b < 32; b++) {
            int idx = w * 32 + b;
            if (idx < COMP && sm[O_H2 + s * HS + idx] > 0.f) m |= 1u << b;
        }
        g_d2m[(sbase + s) * 3 + w] = m;
    }
    layer_fwd<COMP, COMP, ACT_RELU>(sm, O_H1, HS, 0, O_H2, HS, mw3, mb3);
    for (int i = tid; i < TS * COMP; i += FWD_THREADS) {
        int s = i / COMP, o = i - s * COMP;
        g_fout[(sbase + s) * COMP + o] = sm[O_H1 + s * HS + o];
    }
    layer_fwd<KS, CON, ACT_TANH>(sm, O_K1, 33, 0, O_X, XS, kw1, kb1);
    layer_fwd<16, KS, ACT_TANH>(sm, O_K2, 17, 0, O_K1, 33, kw2, kb2);
    if (tid < TS) {
        float z = kb3[0];
        #pragma unroll
        for (int i = 0; i < 16; i++) z = fmaf(sm[O_K2 + tid * 17 + i], kw3[i], z);
        g_kout[sbase + tid] = (z > 20.f) ? z : log1pf(expf(z));
    }
}

// =========================================================================
// Kernel 3: Jacobian norm + final output. R12 structure at 416 threads
// (13 warps/CTA, 2 CTAs/SM -> 26 warps/SM; regs cap 78 = current usage).
// =========================================================================
#define SPC 4          // samples per CTA (sequential)
#define JT 416         // jac threads
#define JW 13          // jac warps

// smem layout (float offsets), stride 88
#define J_CW3   0                // CW3T: n2 x 88 (k-major). Gc overlays after GEMM1.
#define J_CW2   7744             // n2 x 88, pad cols exact 0
#define J_CB    15224            // Bc: 88 x 88
#define J_FROWS 22968            // SPC x 88
#define J_KOUT  23320            // SPC
#define J_MASKS 23324            // 24 unsigned
#define J_ACTL  23348            // SPC*3*88 ints
#define J_CNT   24404            // SPC*3 ints
#define J_WSUM  24416            // 16 (JW=13 used)
#define JAC_SMEM_FLOATS 24432
#define JAC_SMEM_BYTES  (JAC_SMEM_FLOATS * 4)

__global__ __launch_bounds__(JT, 2)
void jac_kernel(const float* __restrict__ mw2, float* __restrict__ out)
{
    extern __shared__ float sm[];
    const int tid = threadIdx.x;
    const int wid = tid >> 5;
    const int lane = tid & 31;
    const int gs0 = blockIdx.x * SPC;
    unsigned* um = (unsigned*)(sm + J_MASKS);
    int* actl = (int*)(sm + J_ACTL);
    int* cnt = (int*)(sm + J_CNT);
    const uint32_t sb = (uint32_t)__cvta_generic_to_shared(sm);

    // ---- hoisted per-CTA setup ----
    for (int i = tid; i < SPC * COMP; i += JT) {
        int s = i / COMP, c = i - s * COMP;
        sm[J_FROWS + s * 88 + c] = g_fout[(gs0 + s) * COMP + c];
    }
    if (tid < SPC) sm[J_KOUT + tid] = g_kout[gs0 + tid];
    if (tid >= 32 && tid < 32 + SPC * 3) um[tid - 32] = g_d1m[gs0 * 3 + tid - 32];
    if (tid >= 64 && tid < 64 + SPC * 3) um[SPC * 3 + tid - 64] = g_d2m[gs0 * 3 + tid - 64];
    __syncthreads();

    // build all SPC*3 = 12 act lists: one per warp (warp 12 idle here)
    if (wid < SPC * 3) {
        int task = wid;   // 0..11
        int s = task / 3, L = task - 3 * s;
        int* act = actl + task * 88;
        int base = 0;
        for (int w = 0; w < 3; w++) {
            unsigned word;
            if (L == 0)      word = um[s * 3 + w];
            else if (L == 1) word = um[SPC * 3 + s * 3 + w];
            else {
                int idx = w * 32 + lane;
                word = __ballot_sync(0xFFFFFFFFu,
                                     idx < COMP && sm[J_FROWS + s * 88 + idx] > 0.f);
            }
            int idx = w * 32 + lane;
            if ((word >> lane) & 1u)
                act[base + __popc(word & ((1u << lane) - 1u))] = idx;
            base += __popc(word);
        }
        if (L != 1) {   // zero-pad act1/act3 so padded gathers stay in-bounds
            int np = (base + 3) & ~3;
            for (int p = base + lane; p < np; p += 32) act[p] = 0;
        }
        if (lane == 0) cnt[task] = base;
    }
    __syncthreads();

    // prologue: prefetch CW2 for sample 0
    {
        const int* act1 = actl + 0 * 88;
        const int* act2 = actl + 1 * 88;
        const int n1 = cnt[0], n2 = cnt[1];
        const int n1p = (n1 + 3) & ~3;
        for (int m = wid; m < n2; m += JW) {
            uint32_t d2 = sb + (J_CW2 + m * 88) * 4;
            const float* s2 = mw2 + act2[m] * COMP;
            for (int j = lane; j < n1p; j += 32) {
                if (j < n1) cpa4(d2 + j * 4, s2 + act1[j]);
                else sm[J_CW2 + m * 88 + j] = 0.f;
            }
        }
    }
    cpa_commit();

    // ---- per-sample loop ----
    for (int ss = 0; ss < SPC; ss++) {
        const int* act1 = actl + (ss * 3 + 0) * 88;
        const int* act2 = actl + (ss * 3 + 1) * 88;
        const int* act3 = actl + (ss * 3 + 2) * 88;
        const int n1 = cnt[ss * 3], n2 = cnt[ss * 3 + 1], n3 = cnt[ss * 3 + 2];
        const int n1p = (n1 + 3) & ~3;
        const int n3p = (n3 + 3) & ~3;
        const int nb1 = n1p >> 2, nb3 = n3p >> 2;

        // P1: gather CW3T[m][i] = W3T[act2[m], act3[i]]  (sorted row gather)
        for (int m = wid; m < n2; m += JW) {
            uint32_t d3 = sb + (J_CW3 + m * 88) * 4;
            const float* s3 = g_W3T + act2[m] * COMP;
            for (int i = lane; i < n3p; i += 32)
                cpa4(d3 + i * 4, s3 + act3[i]);
        }
        cpa_commit();
        cpa_wait<0>();   // drains CW3T + this sample's CW2 prefetch
        __syncthreads();

        // P2: Bc[n3p x n1p] = W3c @ W2c (K = n2), 4x4 tiles, f32x2 FMAs
        for (int t = tid; t < nb3 * nb1; t += JT) {
            int bi = t / nb1, bj = t - bi * nb1;
            int ii = bi << 2, jj = bj << 2;
            unsigned long long a0l=0,a0h=0, a1l=0,a1h=0;
            unsigned long long a2l=0,a2h=0, a3l=0,a3h=0;
            const float* w3t = sm + J_CW3 + ii;
            uint32_t w2a = sb + (J_CW2 + jj) * 4;
            #pragma unroll 4
            for (int kk = 0; kk < n2; kk++) {
                float4 x = *(const float4*)(w3t + kk * 88);
                unsigned long long b01, b23;
                lds_v2u64(w2a + kk * 352, b01, b23);
                unsigned long long x0 = pack2_dup(x.x);
                unsigned long long x1 = pack2_dup(x.y);
                unsigned long long x2 = pack2_dup(x.z);
                unsigned long long x3 = pack2_dup(x.w);
                a0l = fma2(x0, b01, a0l); a0h = fma2(x0, b23, a0h);
                a1l = fma2(x1, b01, a1l); a1h = fma2(x1, b23, a1h);
                a2l = fma2(x2, b01, a2l); a2h = fma2(x2, b23, a2h);
                a3l = fma2(x3, b01, a3l); a3h = fma2(x3, b23, a3h);
            }
            uint32_t cba = sb + (J_CB + ii * 88 + jj) * 4;
            sts_v2u64(cba,        a0l, a0h);
            sts_v2u64(cba + 352,  a1l, a1h);
            sts_v2u64(cba + 704,  a2l, a2h);
            sts_v2u64(cba + 1056, a3l, a3h);
        }
        __syncthreads();

        // P3: Gc gather (group A) + next sample's CW2 prefetch (group B)
        float* gc = sm + J_CW3;
        for (int a = wid; a < n1; a += JW) {    // rows >= n1 stale: s==0 there
            const float* srow = g_G + act1[a] * COMP;
            uint32_t da = sb + (J_CW3 + a * 88) * 4;
            for (int b = lane; b < n1p; b += 32)
                cpa4(da + b * 4, srow + act1[b]);
        }
        cpa_commit();                            // group A
        if (ss + 1 < SPC) {
            const int* act1n = actl + ((ss + 1) * 3 + 0) * 88;
            const int* act2n = actl + ((ss + 1) * 3 + 1) * 88;
            const int n1n = cnt[(ss + 1) * 3], n2n = cnt[(ss + 1) * 3 + 1];
            const int n1pn = (n1n + 3) & ~3;
            for (int m = wid; m < n2n; m += JW) {
                uint32_t d2 = sb + (J_CW2 + m * 88) * 4;
                const float* s2 = mw2 + act2n[m] * COMP;
                for (int j = lane; j < n1pn; j += 32) {
                    if (j < n1n) cpa4(d2 + j * 4, s2 + act1n[j]);
                    else sm[J_CW2 + m * 88 + j] = 0.f;
                }
            }
        }
        cpa_commit();                            // group B (possibly empty)
        cpa_wait<1>();                           // A complete; B flies under trace
        __syncthreads();

        // P4: trace, symmetric 4x4 tiles, split-k=4 (linear in partial S).
        const int ntri = nb1 * (nb1 + 1) / 2;
        const int ntask = ntri << 2;
        float local = 0.f;
        for (int t = tid; t < ntask; t += JT) {
            int tile = t >> 2, part = t & 3;
            int bj = (int)((__fsqrt_rn(8.f * tile + 1.f) - 1.f) * 0.5f);
            while ((bj + 1) * (bj + 2) / 2 <= tile) bj++;
            while (bj * (bj + 1) / 2 > tile) bj--;
            int bi = tile - bj * (bj + 1) / 2;   // bi <= bj
            int aa = bi << 2, bb = bj << 2;
            int k0 = (n3 * part) >> 2;
            int k1 = (n3 * (part + 1)) >> 2;
            unsigned long long s0l=0,s0h=0, s1l=0,s1h=0;
            unsigned long long s2l=0,s2h=0, s3l=0,s3h=0;
            const float* ca = sm + J_CB + aa;
            uint32_t vb = sb + (J_CB + bb) * 4;
            #pragma unroll 4
            for (int kk = k0; kk < k1; kk++) {
                float4 u = *(const float4*)(ca + kk * 88);
                unsigned long long v01, v23;
                lds_v2u64(vb + kk * 352, v01, v23);
                unsigned long long u0 = pack2_dup(u.x);
                unsigned long long u1 = pack2_dup(u.y);
                unsigned long long u2 = pack2_dup(u.z);
                unsigned long long u3 = pack2_dup(u.w);
                s0l = fma2(u0, v01, s0l); s0h = fma2(u0, v23, s0h);
                s1l = fma2(u1, v01, s1l); s1h = fma2(u1, v23, s1h);
                s2l = fma2(u2, v01, s2l); s2h = fma2(u2, v23, s2h);
                s3l = fma2(u3, v01, s3l); s3h = fma2(u3, v23, s3h);
            }
            float s00,s01,s02,s03, s10,s11,s12,s13;
            float s20,s21,s22,s23, s30,s31,s32,s33;
            unpack2(s0l, s00, s01); unpack2(s0h, s02, s03);
            unpack2(s1l, s10, s11); unpack2(s1h, s12, s13);
            unpack2(s2l, s20, s21); unpack2(s2h, s22, s23);
            unpack2(s3l, s30, s31); unpack2(s3h, s32, s33);
            float4 q0 = *(const float4*)(gc + (aa + 0) * 88 + bb);
            float4 q1 = *(const float4*)(gc + (aa + 1) * 88 + bb);
            float4 q2 = *(const float4*)(gc + (aa + 2) * 88 + bb);
            float4 q3 = *(const float4*)(gc + (aa + 3) * 88 + bb);
            if (bi < bj) {
                float p =
                      s00*q0.x + s01*q0.y + s02*q0.z + s03*q0.w
                    + s10*q1.x + s11*q1.y + s12*q1.z + s13*q1.w
                    + s20*q2.x + s21*q2.y + s22*q2.z + s23*q2.w
                    + s30*q3.x + s31*q3.y + s32*q3.z + s33*q3.w;
                local += 2.f * p;
            } else {
                // diagonal tile (aa == bb): weight c>r:2, c==r:1, c<r:0
                local += s00*q0.x + 2.f*(s01*q0.y + s02*q0.z + s03*q0.w)
                       + s11*q1.y + 2.f*(s12*q1.z + s13*q1.w)
                       + s22*q2.z + 2.f*(s23*q2.w)
                       + s33*q3.w;
            }
        }
        #pragma unroll
        for (int off = 16; off; off >>= 1)
            local += __shfl_down_sync(0xFFFFFFFFu, local, off);
        if (lane == 0) sm[J_WSUM + wid] = local;
        __syncthreads();

        // P5: output
        if (tid < COMP) {
            float ns = 0.f;
            #pragma unroll
            for (int w = 0; w < JW; w++) ns += sm[J_WSUM + w];
            float scal = 1.f / (sqrtf(ns) + 1e-4f);
            float kv = sm[J_KOUT + ss];
            out[(gs0 + ss) * COMP + tid] = tanhf(kv * sm[J_FROWS + ss * 88 + tid] * scal);
        }
        __syncthreads();
    }
}

// =========================================================================
// launch
// =========================================================================
extern "C" void kernel_launch(void* const* d_in, const int* in_sizes, int n_in,
                              void* d_out, int out_size)
{
    const float* obs    = (const float*)d_in[0];
    const float* action = (const float*)d_in[1];
    const float* ow1 = (const float*)d_in[2];
    const float* ob1 = (const float*)d_in[3];
    const float* ow2 = (const float*)d_in[4];
    const float* ob2 = (const float*)d_in[5];
    const float* aw1 = (const float*)d_in[6];
    const float* ab1 = (const float*)d_in[7];
    const float* aw2 = (const float*)d_in[8];
    const float* ab2 = (const float*)d_in[9];
    const float* mw1 = (const float*)d_in[10];
    const float* mb1 = (const float*)d_in[11];
    const float* mw2 = (const float*)d_in[12];
    const float* mb2 = (const float*)d_in[13];
    const float* mw3 = (const float*)d_in[14];
    const float* mb3 = (const float*)d_in[15];
    const float* kw1 = (const float*)d_in[16];
    const float* kb1 = (const float*)d_in[17];
    const float* kw2 = (const float*)d_in[18];
    const float* kb2 = (const float*)d_in[19];
    const float* kw3 = (const float*)d_in[20];
    const float* kb3 = (const float*)d_in[21];
    float* out = (float*)d_out;

    cudaFuncSetAttribute(fwd_kernel, cudaFuncAttributeMaxDynamicSharedMemorySize,
                         FWD_SMEM_BYTES);
    cudaFuncSetAttribute(jac_kernel, cudaFuncAttributeMaxDynamicSharedMemorySize,
                         JAC_SMEM_BYTES);

    g_kernel<<<(COMP * COMP * 32 + 255) / 256, 256>>>(mw1, mw3);
    fwd_kernel<<<BATCH / TS, FWD_THREADS, FWD_SMEM_BYTES>>>(
        obs, action, ow1, ob1, ow2, ob2, aw1, ab1, aw2, ab2,
        mw1, mb1, mw2, mb2, mw3, mb3, kw1, kb1, kw2, kb2, kw3, kb3);
    jac_kernel<<<BATCH / SPC, JT, JAC_SMEM_BYTES>>>(mw2, out);
}

// round 17
// speedup vs baseline: 1.2063x; 1.0200x over previous
#include <cuda_runtime.h>
#include <math.h>
#include <stdint.h>

// Problem dims
#define BATCH 8192
#define OBS 64
#define ACT 16
#define HID 128
#define CON 256
#define COMP 85
#define KS 32

// ---------------- scratch (device globals; no allocation) ----------------
__device__ float g_G[COMP * COMP];          // W1 W1^T
__device__ float g_W3T[COMP * COMP];        // mw3 transposed
__device__ float g_fout[BATCH * COMP];      // f-net output (relu(p3))
__device__ float g_kout[BATCH];             // k-net output (softplus)
__device__ unsigned g_d1m[BATCH * 3];       // d1 bitmask (85 bits in 3 words)
__device__ unsigned g_d2m[BATCH * 3];       // d2 bitmask

// ---- cp.async helpers ----
__device__ __forceinline__ void cpa4(uint32_t dst_smem, const float* src) {
    asm volatile("cp.async.ca.shared.global [%0], [%1], 4;"
                 :: "r"(dst_smem), "l"(src));
}
__device__ __forceinline__ void cpa_commit() {
    asm volatile("cp.async.commit_group;" ::: "memory");
}
template<int N>
__device__ __forceinline__ void cpa_wait() {
    asm volatile("cp.async.wait_group %0;" :: "n"(N) : "memory");
}

// ---- packed f32x2 helpers (sm_100a; exact dual fp32 FMA) ----
__device__ __forceinline__ unsigned long long pack2_dup(float x) {
    unsigned long long r;
    uint32_t u = __float_as_uint(x);
    asm("mov.b64 %0, {%1, %2};" : "=l"(r) : "r"(u), "r"(u));
    return r;
}
__device__ __forceinline__ unsigned long long fma2(
    unsigned long long a, unsigned long long b, unsigned long long c) {
    unsigned long long d;
    asm("fma.rn.f32x2 %0, %1, %2, %3;" : "=l"(d) : "l"(a), "l"(b), "l"(c));
    return d;
}
__device__ __forceinline__ void lds_v2u64(uint32_t addr,
                                          unsigned long long& a,
                                          unsigned long long& b) {
    asm volatile("ld.shared.v2.b64 {%0, %1}, [%2];"
                 : "=l"(a), "=l"(b) : "r"(addr));
}
__device__ __forceinline__ void sts_v2u64(uint32_t addr,
                                          unsigned long long a,
                                          unsigned long long b) {
    asm volatile("st.shared.v2.b64 [%0], {%1, %2};"
                 :: "r"(addr), "l"(a), "l"(b) : "memory");
}
__device__ __forceinline__ void unpack2(unsigned long long v, float& lo, float& hi) {
    uint32_t l, h;
    asm("mov.b64 {%0, %1}, %2;" : "=r"(l), "=r"(h) : "l"(v));
    lo = __uint_as_float(l);
    hi = __uint_as_float(h);
}

// =========================================================================
// Kernel 1: G = mw1 @ mw1^T (warp per element) + W3 transpose
// =========================================================================
__global__ __launch_bounds__(256)
void g_kernel(const float* __restrict__ mw1, const float* __restrict__ mw3) {
    int gid = blockIdx.x * 256 + threadIdx.x;
    if (gid < COMP * COMP) {
        int r = gid / COMP, c = gid - r * COMP;
        g_W3T[c * COMP + r] = mw3[gid];
    }
    int gw = gid >> 5;   // global warp id
    int lane = threadIdx.x & 31;
    if (gw >= COMP * COMP) return;
    int i = gw / COMP;
    int j = gw - i * COMP;
    const float4* a = (const float4*)(mw1 + i * CON);
    const float4* b = (const float4*)(mw1 + j * CON);
    float acc = 0.f;
    #pragma unroll
    for (int t = 0; t < 2; t++) {
        float4 av = a[lane + 32 * t];
        float4 bv = b[lane + 32 * t];
        acc += av.x * bv.x + av.y * bv.y + av.z * bv.z + av.w * bv.w;
    }
    #pragma unroll
    for (int off = 16; off; off >>= 1)
        acc += __shfl_down_sync(0xFFFFFFFFu, acc, off);
    if (lane == 0) g_G[gw] = acc;
}

// =========================================================================
// Kernel 2: fused forward pass. 64 samples per CTA, 512 threads,
// 4 samples per 32-thread group (R12 config — best known).
// =========================================================================
#define TS 64
#define FWD_THREADS 512

// smem layout (float offsets)
#define O_X   0            // x buffer 64 x 257 (concat of/af)
#define XS    257
#define O_W   16448        // weight staging 16512 floats
#define O_T   32960        // head layer-1 temp 64 x 129
#define TBS   129
#define O_IN  41216        // input staging 64 x 65 (also k1/k2 bufs)
#define O_K1  41216        // k1: 64 x 33
#define O_K2  43328        // k2: 64 x 17
#define O_H1  45376        // h1 / f_out: 64 x 87
#define O_H2  50944        // h2: 64 x 87
#define HS    87
#define FWD_SMEM_FLOATS 56512
#define FWD_SMEM_BYTES  (FWD_SMEM_FLOATS * 4)

#define ACT_RELU 0
#define ACT_TANH 1

template<int N, int K, int ACTT>
__device__ __forceinline__ void layer_fwd(
    float* __restrict__ sm,
    int o_out, int outStride, int outColOff,
    int o_in, int inStride,
    const float* __restrict__ Wg, const float* __restrict__ bg)
{
    constexpr int NJ = (N + 31) / 32;
    const int tid = threadIdx.x;
    const int sp = tid >> 5;       // 0..15, samples 4sp..4sp+3
    const int q = tid & 31;        // output col group

    float acc[4][NJ];
    #pragma unroll
    for (int s = 0; s < 4; s++)
        #pragma unroll
        for (int j = 0; j < NJ; j++) acc[s][j] = 0.f;

    float* wbuf = sm + O_W;
    constexpr int KC = (K > 128) ? 128 : K;
    constexpr int WS = KC | 1;     // odd stride -> conflict-free weight columns

    #pragma unroll
    for (int k0 = 0; k0 < K; k0 += KC) {
        __syncthreads();
        {
            constexpr int TOT = N * KC;
            constexpr int NIT = (TOT + FWD_THREADS - 1) / FWD_THREADS;
            int i = tid;
            #pragma unroll
            for (int u = 0; u < NIT; u++) {
                if (i < TOT) {
                    int r = i / KC;
                    int c = i - r * KC;
                    wbuf[r * WS + c] = Wg[r * K + k0 + c];
                }
                i += FWD_THREADS;
            }
        }
        __syncthreads();
        const float* in0 = sm + o_in + (4 * sp + 0) * inStride + k0;
        const float* in1 = sm + o_in + (4 * sp + 1) * inStride + k0;
        const float* in2 = sm + o_in + (4 * sp + 2) * inStride + k0;
        const float* in3 = sm + o_in + (4 * sp + 3) * inStride + k0;
        #pragma unroll 2
        for (int k = 0; k < KC; k++) {
            float a0 = in0[k], a1 = in1[k], a2 = in2[k], a3 = in3[k];
            const float* wr = wbuf + k + q * WS;
            #pragma unroll
            for (int j = 0; j < NJ; j++) {
                float w = wr[(j << 5) * WS];
                acc[0][j] = fmaf(a0, w, acc[0][j]);
                acc[1][j] = fmaf(a1, w, acc[1][j]);
                acc[2][j] = fmaf(a2, w, acc[2][j]);
                acc[3][j] = fmaf(a3, w, acc[3][j]);
            }
        }
    }
    #pragma unroll
    for (int j = 0; j < NJ; j++) {
        int o = q + (j << 5);
        if (o < N) {
            float bv = bg[o];
            #pragma unroll
            for (int s = 0; s < 4; s++) {
                float v = acc[s][j] + bv;
                if (ACTT == ACT_RELU) v = fmaxf(v, 0.f);
                else if (ACTT == ACT_TANH) v = tanhf(v);
                sm[o_out + (4 * sp + s) * outStride + outColOff + o] = v;
            }
        }
    }
    __syncthreads();
}

__global__ __launch_bounds__(FWD_THREADS)
void fwd_kernel(
    const float* __restrict__ obs, const float* __restrict__ action,
    const float* __restrict__ ow1, const float* __restrict__ ob1,
    const float* __restrict__ ow2, const float* __restrict__ ob2,
    const float* __restrict__ aw1, const float* __restrict__ ab1,
    const float* __restrict__ aw2, const float* __restrict__ ab2,
    const float* __restrict__ mw1, const float* __restrict__ mb1,
    const float* __restrict__ mw2, const float* __restrict__ mb2,
    const float* __restrict__ mw3, const float* __restrict__ mb3,
    const float* __restrict__ kw1, const float* __restrict__ kb1,
    const float* __restrict__ kw2, const float* __restrict__ kb2,
    const float* __restrict__ kw3, const float* __restrict__ kb3)
{
    extern __shared__ float sm[];
    const int tid = threadIdx.x;
    const int sbase = blockIdx.x * TS;

    for (int i = tid; i < TS * OBS; i += FWD_THREADS) {
        int s = i >> 6, k = i & 63;
        sm[O_IN + s * 65 + k] = obs[(sbase + s) * OBS + k];
    }
    __syncthreads();
    layer_fwd<HID, OBS, ACT_RELU>(sm, O_T, TBS, 0, O_IN, 65, ow1, ob1);
    layer_fwd<HID, HID, ACT_RELU>(sm, O_X, XS, 0, O_T, TBS, ow2, ob2);

    for (int i = tid; i < TS * ACT; i += FWD_THREADS) {
        int s = i >> 4, k = i & 15;
        sm[O_IN + s * 17 + k] = action[(sbase + s) * ACT + k];
    }
    __syncthreads();
    layer_fwd<HID, ACT, ACT_RELU>(sm, O_T, TBS, 0, O_IN, 17, aw1, ab1);
    layer_fwd<HID, HID, ACT_RELU>(sm, O_X, XS, 128, O_T, TBS, aw2, ab2);

    layer_fwd<COMP, CON, ACT_RELU>(sm, O_H1, HS, 0, O_X, XS, mw1, mb1);
    if (tid < TS * 3) {
        int s = tid / 3, w = tid - 3 * s;
        unsigned m = 0;
        for (int b = 0; b < 32; b++) {
            int idx = w * 32 + b;
            if (idx < COMP && sm[O_H1 + s * HS + idx] > 0.f) m |= 1u << b;
        }
        g_d1m[(sbase + s) * 3 + w] = m;
    }
    layer_fwd<COMP, COMP, ACT_RELU>(sm, O_H2, HS, 0, O_H1, HS, mw2, mb2);
    if (tid < TS * 3) {
        int s = tid / 3, w = tid - 3 * s;
        unsigned m = 0;
        for (int b = 0; b < 32; b++) {
            int idx = w * 32 + b;
            if (idx < COMP && sm[O_H2 + s * HS + idx] > 0.f) m |= 1u << b;
        }
        g_d2m[(sbase + s) * 3 + w] = m;
    }
    layer_fwd<COMP, COMP, ACT_RELU>(sm, O_H1, HS, 0, O_H2, HS, mw3, mb3);
    for (int i = tid; i < TS * COMP; i += FWD_THREADS) {
        int s = i / COMP, o = i - s * COMP;
        g_fout[(sbase + s) * COMP + o] = sm[O_H1 + s * HS + o];
    }
    layer_fwd<KS, CON, ACT_TANH>(sm, O_K1, 33, 0, O_X, XS, kw1, kb1);
    layer_fwd<16, KS, ACT_TANH>(sm, O_K2, 17, 0, O_K1, 33, kw2, kb2);
    if (tid < TS) {
        float z = kb3[0];
        #pragma unroll
        for (int i = 0; i < 16; i++) z = fmaf(sm[O_K2 + tid * 17 + i], kw3[i], z);
        g_kout[sbase + tid] = (z > 20.f) ? z : log1pf(expf(z));
    }
}

// =========================================================================
// Kernel 3: Jacobian norm + final output. R16 structure at 448 threads
// (14 warps/CTA, 2 CTAs/SM -> 28 warps/SM; reg cap 73).
// =========================================================================
#define SPC 4          // samples per CTA (sequential)
#define JT 448         // jac threads
#define JW 14          // jac warps

// smem layout (float offsets), stride 88
#define J_CW3   0                // CW3T: n2 x 88 (k-major). Gc overlays after GEMM1.
#define J_CW2   7744             // n2 x 88, pad cols exact 0
#define J_CB    15224            // Bc: 88 x 88
#define J_FROWS 22968            // SPC x 88
#define J_KOUT  23320            // SPC
#define J_MASKS 23324            // 24 unsigned
#define J_ACTL  23348            // SPC*3*88 ints
#define J_CNT   24404            // SPC*3 ints
#define J_WSUM  24416            // 16 (JW=14 used)
#define JAC_SMEM_FLOATS 24432
#define JAC_SMEM_BYTES  (JAC_SMEM_FLOATS * 4)

__global__ __launch_bounds__(JT, 2)
void jac_kernel(const float* __restrict__ mw2, float* __restrict__ out)
{
    extern __shared__ float sm[];
    const int tid = threadIdx.x;
    const int wid = tid >> 5;
    const int lane = tid & 31;
    const int gs0 = blockIdx.x * SPC;
    unsigned* um = (unsigned*)(sm + J_MASKS);
    int* actl = (int*)(sm + J_ACTL);
    int* cnt = (int*)(sm + J_CNT);
    const uint32_t sb = (uint32_t)__cvta_generic_to_shared(sm);

    // ---- hoisted per-CTA setup ----
    for (int i = tid; i < SPC * COMP; i += JT) {
        int s = i / COMP, c = i - s * COMP;
        sm[J_FROWS + s * 88 + c] = g_fout[(gs0 + s) * COMP + c];
    }
    if (tid < SPC) sm[J_KOUT + tid] = g_kout[gs0 + tid];
    if (tid >= 32 && tid < 32 + SPC * 3) um[tid - 32] = g_d1m[gs0 * 3 + tid - 32];
    if (tid >= 64 && tid < 64 + SPC * 3) um[SPC * 3 + tid - 64] = g_d2m[gs0 * 3 + tid - 64];
    __syncthreads();

    // build all SPC*3 = 12 act lists: one per warp (warps 12-13 idle here)
    if (wid < SPC * 3) {
        int task = wid;   // 0..11
        int s = task / 3, L = task - 3 * s;
        int* act = actl + task * 88;
        int base = 0;
        for (int w = 0; w < 3; w++) {
            unsigned word;
            if (L == 0)      word = um[s * 3 + w];
            else if (L == 1) word = um[SPC * 3 + s * 3 + w];
            else {
                int idx = w * 32 + lane;
                word = __ballot_sync(0xFFFFFFFFu,
                                     idx < COMP && sm[J_FROWS + s * 88 + idx] > 0.f);
            }
            int idx = w * 32 + lane;
            if ((word >> lane) & 1u)
                act[base + __popc(word & ((1u << lane) - 1u))] = idx;
            base += __popc(word);
        }
        if (L != 1) {   // zero-pad act1/act3 so padded gathers stay in-bounds
            int np = (base + 3) & ~3;
            for (int p = base + lane; p < np; p += 32) act[p] = 0;
        }
        if (lane == 0) cnt[task] = base;
    }
    __syncthreads();

    // prologue: prefetch CW2 for sample 0
    {
        const int* act1 = actl + 0 * 88;
        const int* act2 = actl + 1 * 88;
        const int n1 = cnt[0], n2 = cnt[1];
        const int n1p = (n1 + 3) & ~3;
        for (int m = wid; m < n2; m += JW) {
            uint32_t d2 = sb + (J_CW2 + m * 88) * 4;
            const float* s2 = mw2 + act2[m] * COMP;
            for (int j = lane; j < n1p; j += 32) {
                if (j < n1) cpa4(d2 + j * 4, s2 + act1[j]);
                else sm[J_CW2 + m * 88 + j] = 0.f;
            }
        }
    }
    cpa_commit();

    // ---- per-sample loop ----
    for (int ss = 0; ss < SPC; ss++) {
        const int* act1 = actl + (ss * 3 + 0) * 88;
        const int* act2 = actl + (ss * 3 + 1) * 88;
        const int* act3 = actl + (ss * 3 + 2) * 88;
        const int n1 = cnt[ss * 3], n2 = cnt[ss * 3 + 1], n3 = cnt[ss * 3 + 2];
        const int n1p = (n1 + 3) & ~3;
        const int n3p = (n3 + 3) & ~3;
        const int nb1 = n1p >> 2, nb3 = n3p >> 2;

        // P1: gather CW3T[m][i] = W3T[act2[m], act3[i]]  (sorted row gather)
        for (int m = wid; m < n2; m += JW) {
            uint32_t d3 = sb + (J_CW3 + m * 88) * 4;
            const float* s3 = g_W3T + act2[m] * COMP;
            for (int i = lane; i < n3p; i += 32)
                cpa4(d3 + i * 4, s3 + act3[i]);
        }
        cpa_commit();
        cpa_wait<0>();   // drains CW3T + this sample's CW2 prefetch
        __syncthreads();

        // P2: Bc[n3p x n1p] = W3c @ W2c (K = n2), 4x4 tiles, f32x2 FMAs
        for (int t = tid; t < nb3 * nb1; t += JT) {
            int bi = t / nb1, bj = t - bi * nb1;
            int ii = bi << 2, jj = bj << 2;
            unsigned long long a0l=0,a0h=0, a1l=0,a1h=0;
            unsigned long long a2l=0,a2h=0, a3l=0,a3h=0;
            const float* w3t = sm + J_CW3 + ii;
            uint32_t w2a = sb + (J_CW2 + jj) * 4;
            #pragma unroll 4
            for (int kk = 0; kk < n2; kk++) {
                float4 x = *(const float4*)(w3t + kk * 88);
                unsigned long long b01, b23;
                lds_v2u64(w2a + kk * 352, b01, b23);
                unsigned long long x0 = pack2_dup(x.x);
                unsigned long long x1 = pack2_dup(x.y);
                unsigned long long x2 = pack2_dup(x.z);
                unsigned long long x3 = pack2_dup(x.w);
                a0l = fma2(x0, b01, a0l); a0h = fma2(x0, b23, a0h);
                a1l = fma2(x1, b01, a1l); a1h = fma2(x1, b23, a1h);
                a2l = fma2(x2, b01, a2l); a2h = fma2(x2, b23, a2h);
                a3l = fma2(x3, b01, a3l); a3h = fma2(x3, b23, a3h);
            }
            uint32_t cba = sb + (J_CB + ii * 88 + jj) * 4;
            sts_v2u64(cba,        a0l, a0h);
            sts_v2u64(cba + 352,  a1l, a1h);
            sts_v2u64(cba + 704,  a2l, a2h);
            sts_v2u64(cba + 1056, a3l, a3h);
        }
        __syncthreads();

        // P3: Gc gather (group A) + next sample's CW2 prefetch (group B)
        float* gc = sm + J_CW3;
        for (int a = wid; a < n1; a += JW) {    // rows >= n1 stale: s==0 there
            const float* srow = g_G + act1[a] * COMP;
            uint32_t da = sb + (J_CW3 + a * 88) * 4;
            for (int b = lane; b < n1p; b += 32)
                cpa4(da + b * 4, srow + act1[b]);
        }
        cpa_commit();                            // group A
        if (ss + 1 < SPC) {
            const int* act1n = actl + ((ss + 1) * 3 + 0) * 88;
            const int* act2n = actl + ((ss + 1) * 3 + 1) * 88;
            const int n1n = cnt[(ss + 1) * 3], n2n = cnt[(ss + 1) * 3 + 1];
            const int n1pn = (n1n + 3) & ~3;
            for (int m = wid; m < n2n; m += JW) {
                uint32_t d2 = sb + (J_CW2 + m * 88) * 4;
                const float* s2 = mw2 + act2n[m] * COMP;
                for (int j = lane; j < n1pn; j += 32) {
                    if (j < n1n) cpa4(d2 + j * 4, s2 + act1n[j]);
                    else sm[J_CW2 + m * 88 + j] = 0.f;
                }
            }
        }
        cpa_commit();                            // group B (possibly empty)
        cpa_wait<1>();                           // A complete; B flies under trace
        __syncthreads();

        // P4: trace, symmetric 4x4 tiles, split-k=4 (linear in partial S).
        const int ntri = nb1 * (nb1 + 1) / 2;
        const int ntask = ntri << 2;
        float local = 0.f;
        for (int t = tid; t < ntask; t += JT) {
            int tile = t >> 2, part = t & 3;
            int bj = (int)((__fsqrt_rn(8.f * tile + 1.f) - 1.f) * 0.5f);
            while ((bj + 1) * (bj + 2) / 2 <= tile) bj++;
            while (bj * (bj + 1) / 2 > tile) bj--;
            int bi = tile - bj * (bj + 1) / 2;   // bi <= bj
            int aa = bi << 2, bb = bj << 2;
            int k0 = (n3 * part) >> 2;
            int k1 = (n3 * (part + 1)) >> 2;
            unsigned long long s0l=0,s0h=0, s1l=0,s1h=0;
            unsigned long long s2l=0,s2h=0, s3l=0,s3h=0;
            const float* ca = sm + J_CB + aa;
            uint32_t vb = sb + (J_CB + bb) * 4;
            #pragma unroll 4
            for (int kk = k0; kk < k1; kk++) {
                float4 u = *(const float4*)(ca + kk * 88);
                unsigned long long v01, v23;
                lds_v2u64(vb + kk * 352, v01, v23);
                unsigned long long u0 = pack2_dup(u.x);
                unsigned long long u1 = pack2_dup(u.y);
                unsigned long long u2 = pack2_dup(u.z);
                unsigned long long u3 = pack2_dup(u.w);
                s0l = fma2(u0, v01, s0l); s0h = fma2(u0, v23, s0h);
                s1l = fma2(u1, v01, s1l); s1h = fma2(u1, v23, s1h);
                s2l = fma2(u2, v01, s2l); s2h = fma2(u2, v23, s2h);
                s3l = fma2(u3, v01, s3l); s3h = fma2(u3, v23, s3h);
            }
            float s00,s01,s02,s03, s10,s11,s12,s13;
            float s20,s21,s22,s23, s30,s31,s32,s33;
            unpack2(s0l, s00, s01); unpack2(s0h, s02, s03);
            unpack2(s1l, s10, s11); unpack2(s1h, s12, s13);
            unpack2(s2l, s20, s21); unpack2(s2h, s22, s23);
            unpack2(s3l, s30, s31); unpack2(s3h, s32, s33);
            float4 q0 = *(const float4*)(gc + (aa + 0) * 88 + bb);
            float4 q1 = *(const float4*)(gc + (aa + 1) * 88 + bb);
            float4 q2 = *(const float4*)(gc + (aa + 2) * 88 + bb);
            float4 q3 = *(const float4*)(gc + (aa + 3) * 88 + bb);
            if (bi < bj) {
                float p =
                      s00*q0.x + s01*q0.y + s02*q0.z + s03*q0.w
                    + s10*q1.x + s11*q1.y + s12*q1.z + s13*q1.w
                    + s20*q2.x + s21*q2.y + s22*q2.z + s23*q2.w
                    + s30*q3.x + s31*q3.y + s32*q3.z + s33*q3.w;
                local += 2.f * p;
            } else {
                // diagonal tile (aa == bb): weight c>r:2, c==r:1, c<r:0
                local += s00*q0.x + 2.f*(s01*q0.y + s02*q0.z + s03*q0.w)
                       + s11*q1.y + 2.f*(s12*q1.z + s13*q1.w)
                       + s22*q2.z + 2.f*(s23*q2.w)
                       + s33*q3.w;
            }
        }
        #pragma unroll
        for (int off = 16; off; off >>= 1)
            local += __shfl_down_sync(0xFFFFFFFFu, local, off);
        if (lane == 0) sm[J_WSUM + wid] = local;
        __syncthreads();

        // P5: output. (No end-of-loop barrier: gc reads all completed before
        // the barrier above; WSUM next written only after 3 more barriers.)
        if (tid < COMP) {
            float ns = 0.f;
            #pragma unroll
            for (int w = 0; w < JW; w++) ns += sm[J_WSUM + w];
            float scal = 1.f / (sqrtf(ns) + 1e-4f);
            float kv = sm[J_KOUT + ss];
            out[(gs0 + ss) * COMP + tid] = tanhf(kv * sm[J_FROWS + ss * 88 + tid] * scal);
        }
    }
}

// =========================================================================
// launch
// =========================================================================
extern "C" void kernel_launch(void* const* d_in, const int* in_sizes, int n_in,
                              void* d_out, int out_size)
{
    const float* obs    = (const float*)d_in[0];
    const float* action = (const float*)d_in[1];
    const float* ow1 = (const float*)d_in[2];
    const float* ob1 = (const float*)d_in[3];
    const float* ow2 = (const float*)d_in[4];
    const float* ob2 = (const float*)d_in[5];
    const float* aw1 = (const float*)d_in[6];
    const float* ab1 = (const float*)d_in[7];
    const float* aw2 = (const float*)d_in[8];
    const float* ab2 = (const float*)d_in[9];
    const float* mw1 = (const float*)d_in[10];
    const float* mb1 = (const float*)d_in[11];
    const float* mw2 = (const float*)d_in[12];
    const float* mb2 = (const float*)d_in[13];
    const float* mw3 = (const float*)d_in[14];
    const float* mb3 = (const float*)d_in[15];
    const float* kw1 = (const float*)d_in[16];
    const float* kb1 = (const float*)d_in[17];
    const float* kw2 = (const float*)d_in[18];
    const float* kb2 = (const float*)d_in[19];
    const float* kw3 = (const float*)d_in[20];
    const float* kb3 = (const float*)d_in[21];
    float* out = (float*)d_out;

    cudaFuncSetAttribute(fwd_kernel, cudaFuncAttributeMaxDynamicSharedMemorySize,
                         FWD_SMEM_BYTES);
    cudaFuncSetAttribute(jac_kernel, cudaFuncAttributeMaxDynamicSharedMemorySize,
                         JAC_SMEM_BYTES);

    g_kernel<<<(COMP * COMP * 32 + 255) / 256, 256>>>(mw1, mw3);
    fwd_kernel<<<BATCH / TS, FWD_THREADS, FWD_SMEM_BYTES>>>(
        obs, action, ow1, ob1, ow2, ob2, aw1, ab1, aw2, ab2,
        mw1, mb1, mw2, mb2, mw3, mb3, kw1, kb1, kw2, kb2, kw3, kb3);
    jac_kernel<<<BATCH / SPC, JT, JAC_SMEM_BYTES>>>(mw2, out);
}